// round 12
// baseline (speedup 1.0000x reference)
#include <cuda_runtime.h>
#include <cuda_bf16.h>

#define BB 4
#define NN 2048
#define TOPK 10

typedef unsigned long long u64;
typedef unsigned int u32;

// Scratch (device globals — no allocation in kernel_launch)
__device__ __align__(128) float g_q  [(size_t)BB * NN * 64];
__device__ __align__(128) float g_k  [(size_t)BB * NN * 64];
__device__ __align__(128) float g_deg  [BB * NN];     // 0.3*rowsum(prior)
__device__ __align__(128) float g_degsp[BB * NN];     // sparse degree contributions
__device__ __align__(128) float g_spv[BB * NN * 16];  // sparse values
__device__ __align__(128) int   g_spi[BB * NN * 16];  // sparse col indices
__device__ __align__(128) int   g_spc[BB * NN];       // sparse counts
// mma fragments: A (q) hi/lo: [b][rb(128)][h][lane] ; B (k): [b][h][NT(256)][lane]
__device__ __align__(128) uint4 g_qa_hi[4 * 128 * 4 * 32];
__device__ __align__(128) uint4 g_qa_lo[4 * 128 * 4 * 32];
__device__ __align__(128) uint4 g_kb  [4 * 4 * 256 * 32];

__device__ __forceinline__ void mma_bf16(float& d0, float& d1, float& d2, float& d3,
                                         u32 a0, u32 a1, u32 a2, u32 a3,
                                         u32 b0, u32 b1)
{
    asm volatile(
        "mma.sync.aligned.m16n8k16.row.col.f32.bf16.bf16.f32 "
        "{%0,%1,%2,%3},{%4,%5,%6,%7},{%8,%9},{%0,%1,%2,%3};"
        : "+f"(d0), "+f"(d1), "+f"(d2), "+f"(d3)
        : "r"(a0), "r"(a1), "r"(a2), "r"(a3), "r"(b0), "r"(b1));
}
__device__ __forceinline__ float ex2(float x) {
    float r; asm("ex2.approx.f32 %0, %1;" : "=f"(r) : "f"(x));
    return r;
}
__device__ __forceinline__ u32 redux_min_u32(u32 x) {
    u32 r; asm("redux.sync.min.u32 %0, %1, 0xffffffff;" : "=r"(r) : "r"(x));
    return r;
}
__device__ __forceinline__ void bsplit(float x, unsigned short& h, unsigned short& l) {
    __nv_bfloat16 bh = __float2bfloat16(x);
    h = __bfloat16_as_ushort(bh);
    l = __bfloat16_as_ushort(__float2bfloat16(x - __bfloat162float(bh)));
}
__device__ __forceinline__ u32 pk(unsigned short a, unsigned short b) {
    return (u32)a | ((u32)b << 16);
}

// ---------------------------------------------------------------------------
// Kernel A: encoders + fusion + Q/K projections.
// 1 warp = 4 nodes: weight elements are loaded ONCE per warp and applied to
// all 4 nodes (per-node LDG count drops 512 -> 128; this kernel was LSU-issue
// bound). FFMA accumulation order per node is unchanged (bit-identical).
// ---------------------------------------------------------------------------
__global__ __launch_bounds__(256) void k_encode(
    const float* __restrict__ xd, const float* __restrict__ xs,
    const float* __restrict__ Wd, const float* __restrict__ bd,
    const float* __restrict__ Ws, const float* __restrict__ bs,
    const float* __restrict__ Wf, const float* __restrict__ bf,
    const float* __restrict__ Wq, const float* __restrict__ Wk)
{
    __shared__ float cat_s[32][128];
    __shared__ float h_s[32][64];
    int tid = threadIdx.x, w = tid >> 5, l = tid & 31;
    int nb = blockIdx.x * 32 + w * 4;            // first node of this warp
    int s4 = w * 4;

    // mean over T (lane l<16 ends holding feature l) + static feature regs
    float xm[4], xsv[4];
    #pragma unroll
    for (int j = 0; j < 4; ++j) {
        const float* xp = xd + (size_t)(nb + j) * 512;
        int dd = l & 15, hh = l >> 4;
        float s = 0.f;
        #pragma unroll
        for (int t = hh; t < 32; t += 2) s += xp[t * 16 + dd];
        s += __shfl_xor_sync(0xffffffffu, s, 16);
        xm[j] = s * (1.0f / 32.0f);
        xsv[j] = (l < 8) ? xs[(size_t)(nb + j) * 8 + l] : 0.f;
        if (l == 0) g_degsp[nb + j] = 0.f;
    }

    // temporal encoder
    float bdl = bd[l], bdh = bd[l + 32];
    float h1a[4], h1b[4];
    #pragma unroll
    for (int j = 0; j < 4; ++j) { h1a[j] = bdl; h1b[j] = bdh; }
    #pragma unroll
    for (int d = 0; d < 16; ++d) {
        float w0 = Wd[d * 64 + l], w1 = Wd[d * 64 + l + 32];
        #pragma unroll
        for (int j = 0; j < 4; ++j) {
            float x = __shfl_sync(0xffffffffu, xm[j], d);
            h1a[j] += x * w0; h1b[j] += x * w1;
        }
    }
    #pragma unroll
    for (int j = 0; j < 4; ++j) {
        cat_s[s4 + j][l]      = fmaxf(h1a[j], 0.f);
        cat_s[s4 + j][l + 32] = fmaxf(h1b[j], 0.f);
    }

    // static encoder
    float bsl = bs[l], bsh = bs[l + 32];
    #pragma unroll
    for (int j = 0; j < 4; ++j) { h1a[j] = bsl; h1b[j] = bsh; }
    #pragma unroll
    for (int d = 0; d < 8; ++d) {
        float w0 = Ws[d * 64 + l], w1 = Ws[d * 64 + l + 32];
        #pragma unroll
        for (int j = 0; j < 4; ++j) {
            float x = __shfl_sync(0xffffffffu, xsv[j], d);
            h1a[j] += x * w0; h1b[j] += x * w1;
        }
    }
    #pragma unroll
    for (int j = 0; j < 4; ++j) {
        cat_s[s4 + j][64 + l] = fmaxf(h1a[j], 0.f);
        cat_s[s4 + j][96 + l] = fmaxf(h1b[j], 0.f);
    }
    __syncwarp();

    // fusion
    float bfl = bf[l], bfh = bf[l + 32];
    float ha[4], hb[4];
    #pragma unroll
    for (int j = 0; j < 4; ++j) { ha[j] = bfl; hb[j] = bfh; }
    #pragma unroll 8
    for (int i = 0; i < 128; ++i) {
        float w0 = Wf[i * 64 + l], w1 = Wf[i * 64 + l + 32];
        #pragma unroll
        for (int j = 0; j < 4; ++j) {
            float c = cat_s[s4 + j][i];
            ha[j] += c * w0; hb[j] += c * w1;
        }
    }
    #pragma unroll
    for (int j = 0; j < 4; ++j) {
        h_s[s4 + j][l] = ha[j]; h_s[s4 + j][l + 32] = hb[j];
    }
    __syncwarp();

    // q = h@Wq, k = h@Wk
    float qa[4], qb[4], k1[4], k2[4];
    #pragma unroll
    for (int j = 0; j < 4; ++j) { qa[j] = qb[j] = k1[j] = k2[j] = 0.f; }
    #pragma unroll 8
    for (int i = 0; i < 64; ++i) {
        float wq0 = Wq[i * 64 + l], wq1 = Wq[i * 64 + l + 32];
        float wk0 = Wk[i * 64 + l], wk1 = Wk[i * 64 + l + 32];
        #pragma unroll
        for (int j = 0; j < 4; ++j) {
            float hv = h_s[s4 + j][i];
            qa[j] += hv * wq0; qb[j] += hv * wq1;
            k1[j] += hv * wk0; k2[j] += hv * wk1;
        }
    }
    #pragma unroll
    for (int j = 0; j < 4; ++j) {
        size_t node = nb + j;
        g_q[node * 64 + l]      = qa[j];
        g_q[node * 64 + l + 32] = qb[j];
        g_k[node * 64 + l]      = k1[j];
        g_k[node * 64 + l + 32] = k2[j];
    }
}

// ---------------------------------------------------------------------------
// Kernel A2: pack q/K into mma.sync m16n8k16 fragment order (bf16 hi/lo).
// q pre-scaled by 0.25*log2(e) so the MMA result feeds ex2 directly.
// ---------------------------------------------------------------------------
__global__ __launch_bounds__(256) void k_frag()
{
    int t = blockIdx.x * 256 + threadIdx.x;
    const float sc = 0.25f * 1.4426950408889634f;
    if (t < 65536) {
        int lane = t & 31, h = (t >> 5) & 3, rb = (t >> 7) & 127, b = t >> 14;
        int g = lane >> 2, k0 = (lane & 3) * 2;
        int r0 = rb * 16 + g;
        const float* q0 = g_q + ((size_t)(b * 2048 + r0))     * 64 + h * 16;
        const float* q1 = g_q + ((size_t)(b * 2048 + r0 + 8)) * 64 + h * 16;
        unsigned short hh[8], ll[8];
        bsplit(q0[k0]     * sc, hh[0], ll[0]); bsplit(q0[k0 + 1] * sc, hh[1], ll[1]);
        bsplit(q1[k0]     * sc, hh[2], ll[2]); bsplit(q1[k0 + 1] * sc, hh[3], ll[3]);
        bsplit(q0[k0 + 8] * sc, hh[4], ll[4]); bsplit(q0[k0 + 9] * sc, hh[5], ll[5]);
        bsplit(q1[k0 + 8] * sc, hh[6], ll[6]); bsplit(q1[k0 + 9] * sc, hh[7], ll[7]);
        uint4 H, L;
        H.x = pk(hh[0], hh[1]); H.y = pk(hh[2], hh[3]);
        H.z = pk(hh[4], hh[5]); H.w = pk(hh[6], hh[7]);
        L.x = pk(ll[0], ll[1]); L.y = pk(ll[2], ll[3]);
        L.z = pk(ll[4], ll[5]); L.w = pk(ll[6], ll[7]);
        g_qa_hi[t] = H; g_qa_lo[t] = L;
    } else if (t < 65536 + 131072) {
        int t2 = t - 65536;
        int lane = t2 & 31, NT = (t2 >> 5) & 255, h = (t2 >> 13) & 3, b = t2 >> 15;
        int n = NT * 8 + (lane >> 2), k0 = (lane & 3) * 2;
        const float* kp = g_k + ((size_t)(b * 2048 + n)) * 64 + h * 16;
        unsigned short hh[4], ll[4];
        bsplit(kp[k0],     hh[0], ll[0]); bsplit(kp[k0 + 1], hh[1], ll[1]);
        bsplit(kp[k0 + 8], hh[2], ll[2]); bsplit(kp[k0 + 9], hh[3], ll[3]);
        uint4 V;
        V.x = pk(hh[0], hh[1]); V.y = pk(hh[2], hh[3]);
        V.z = pk(ll[0], ll[1]); V.w = pk(ll[2], ll[3]);
        g_kb[t2] = V;
    }
}

// ---------------------------------------------------------------------------
// Kernel B (attention + FUSED blend): 16 rows/block, 512 threads, lb(512,1).
// Per head: MMA (bf16 hi/lo) + ex2 once; ONE barrier per head; every warp
// redundantly computes all 16 row sums. After each head's Arow update, warp w
// streams a quarter of prior row (n0+w): af = 0.3*prior -> A_final, L=-af,
// accumulating 0.3*rowsum(prior). Top-10 per row in u32 domain + redux.sync.
// ---------------------------------------------------------------------------
#define ASTRIDE 2056
__global__ __launch_bounds__(512, 1) void k_attn(
    const float* __restrict__ prior, float* __restrict__ outp)
{
    extern __shared__ float smem[];
    float* Arow = smem;                          // 16 * 2056
    float* red  = smem + 16 * ASTRIDE;           // 2 buffers * 16 rows * 17
    int*   scnt = (int*)(red + 2 * 16 * 17);     // 16

    int tid = threadIdx.x, w = tid >> 5, l = tid & 31;
    int g = l >> 2, tig = l & 3;
    int b  = blockIdx.x >> 7;
    int rb = blockIdx.x & 127;
    int n0 = rb * 16;

    int qidx = (((b * 128 + rb) * 4) << 5) + l;
    const uint4* kb0 = g_kb + (((b * 4) * 256 + w * 16) << 5) + l;

    const size_t OFF = (size_t)BB * NN * NN;
    size_t rowbase = ((size_t)(b * 2048 + n0 + w)) * 2048;
    const float4* pr4 = (const float4*)(prior + rowbase) + l;
    float4* oA4 = (float4*)(outp + OFF + rowbase) + l;
    float4* oL4 = (float4*)(outp + rowbase) + l;
    float psum = 0.f;                            // 0.3*rowsum(prior) partial

    if (tid < 16) scnt[tid] = 0;

    #pragma unroll 1
    for (int h = 0; h < 4; ++h) {
        uint4 AH = g_qa_hi[qidx + (h << 5)];
        uint4 AL = g_qa_lo[qidx + (h << 5)];
        const uint4* kbp = kb0 + ((h * 256) << 5);

        float acc[64];
        #pragma unroll
        for (int t = 0; t < 16; ++t) {
            uint4 BV = kbp[t << 5];
            float d0 = 0.f, d1 = 0.f, d2 = 0.f, d3 = 0.f;
            mma_bf16(d0, d1, d2, d3, AH.x, AH.y, AH.z, AH.w, BV.x, BV.y);
            mma_bf16(d0, d1, d2, d3, AH.x, AH.y, AH.z, AH.w, BV.z, BV.w);
            mma_bf16(d0, d1, d2, d3, AL.x, AL.y, AL.z, AL.w, BV.x, BV.y);
            acc[t*4]   = d0; acc[t*4+1] = d1;
            acc[t*4+2] = d2; acc[t*4+3] = d3;
        }

        // exp2 + per-row partial sums
        float rsl = 0.f, rsh = 0.f;
        #pragma unroll
        for (int t = 0; t < 16; ++t) {
            float e0 = ex2(acc[t*4]),   e1 = ex2(acc[t*4+1]);
            float e2 = ex2(acc[t*4+2]), e3 = ex2(acc[t*4+3]);
            acc[t*4] = e0; acc[t*4+1] = e1; acc[t*4+2] = e2; acc[t*4+3] = e3;
            rsl += e0 + e1; rsh += e2 + e3;
        }
        rsl += __shfl_xor_sync(0xffffffffu, rsl, 1);
        rsl += __shfl_xor_sync(0xffffffffu, rsl, 2);
        rsh += __shfl_xor_sync(0xffffffffu, rsh, 1);
        rsh += __shfl_xor_sync(0xffffffffu, rsh, 2);
        float* rbuf = red + (h & 1) * 272;       // 16 rows * 17
        if (tig == 0) {
            rbuf[g * 17 + w]       = rsl;
            rbuf[(g + 8) * 17 + w] = rsh;
        }
        __syncthreads();                          // the ONLY barrier this head

        // every warp: lane l computes sum of row (l & 15) via fixed tree
        float invl, invh;
        {
            const float* rp = rbuf + (l & 15) * 17;
            float s0 = rp[0]  + rp[1],  s1 = rp[2]  + rp[3];
            float s2 = rp[4]  + rp[5],  s3 = rp[6]  + rp[7];
            float s4 = rp[8]  + rp[9],  s5 = rp[10] + rp[11];
            float s6 = rp[12] + rp[13], s7 = rp[14] + rp[15];
            s0 += s1; s2 += s3; s4 += s5; s6 += s7;
            s0 += s2; s4 += s6;
            float sv = 0.25f / (s0 + s4);        // 1/4 head-average folded in
            invl = __shfl_sync(0xffffffffu, sv, g);
            invh = __shfl_sync(0xffffffffu, sv, g + 8);
        }

        float2* A2 = (float2*)Arow;              // row stride 1028 float2
        if (h == 0) {
            #pragma unroll
            for (int t = 0; t < 16; ++t) {
                int c2 = w * 64 + t * 4 + tig;
                A2[g * 1028 + c2]       = make_float2(acc[t*4]   * invl, acc[t*4+1] * invl);
                A2[(g + 8) * 1028 + c2] = make_float2(acc[t*4+2] * invh, acc[t*4+3] * invh);
            }
        } else {
            #pragma unroll
            for (int t = 0; t < 16; ++t) {
                int c2 = w * 64 + t * 4 + tig;
                float2 lo = A2[g * 1028 + c2];
                float2 hi = A2[(g + 8) * 1028 + c2];
                lo.x += acc[t*4]   * invl; lo.y += acc[t*4+1] * invl;
                hi.x += acc[t*4+2] * invh; hi.y += acc[t*4+3] * invh;
                A2[g * 1028 + c2]       = lo;
                A2[(g + 8) * 1028 + c2] = hi;
            }
        }

        // ---- fused blend: quarter of prior row (n0+w), cols [h*512, h*512+512)
        {
            int cbase = h * 128;                 // float4 index base of chunk
            #pragma unroll
            for (int i = 0; i < 4; ++i) {
                int c = cbase + i * 32;
                float4 p = pr4[c];
                float4 af = make_float4(0.3f * p.x, 0.3f * p.y,
                                        0.3f * p.z, 0.3f * p.w);
                oA4[c] = af;
                oL4[c] = make_float4(-af.x, -af.y, -af.z, -af.w);
                psum += (af.x + af.y) + (af.z + af.w);
            }
        }
    }

    // degree = 0.3*rowsum(prior): warp-local deterministic reduce
    #pragma unroll
    for (int off = 16; off; off >>= 1)
        psum += __shfl_xor_sync(0xffffffffu, psum, off);
    if (l == 0) g_deg[b * 2048 + n0 + w] = psum;

    __syncthreads();                              // Arow complete for all warps

    // ---- warp w: top-10 of row w in u32 order-isomorphic domain ----
    u32 vi[64];
    const u32* Au = (const u32*)(Arow + w * ASTRIDE);
    #pragma unroll
    for (int i = 0; i < 64; ++i) vi[i] = Au[i * 32 + l];

    u32 c = 0xFFFFFFFFu;
    #pragma unroll 1
    for (int t = 0; t < TOPK; ++t) {
        u32 m0 = 0xFFFFFFFFu, m1 = 0xFFFFFFFFu;
        u32 m2 = 0xFFFFFFFFu, m3 = 0xFFFFFFFFu;
        #pragma unroll
        for (int j = 0; j < 16; ++j) {
            m0 = min(m0, c - vi[4*j+0]);
            m1 = min(m1, c - vi[4*j+1]);
            m2 = min(m2, c - vi[4*j+2]);
            m3 = min(m3, c - vi[4*j+3]);
        }
        u32 dm = redux_min_u32(min(min(m0, m1), min(m2, m3)));
        c = (c - dm) - 1;                        // c = t-th largest - 1
    }
    u32 thr_u = c + 1;                           // 10th-largest bits

    // ---- sparse emit ----
    int row = b * 2048 + n0 + w;
    #pragma unroll
    for (int i = 0; i < 64; ++i) {
        u32 x = vi[i];
        if (x >= thr_u) {
            int p = atomicAdd(&scnt[w], 1);
            if (p < 16) {
                g_spv[row * 16 + p] = __uint_as_float(x);
                g_spi[row * 16 + p] = i * 32 + l;
            }
        }
    }
    __syncwarp();
    if (l == 0) g_spc[row] = min(scnt[w], 16);
}

// ---------------------------------------------------------------------------
// Kernel C2: scatter sparse symmetric contributions into A_final, L, degree.
// Row-side degree contributions are reduced across the 16 slot-lanes (one
// aligned half-warp per row) to a single atomicAdd instead of up to 10
// contended ones.
// ---------------------------------------------------------------------------
__global__ __launch_bounds__(256) void k_scatter(float* __restrict__ out)
{
    int t = blockIdx.x * 256 + threadIdx.x;      // 131072 = 8192 rows * 16
    int row = t >> 4, slot = t & 15;
    int cnt = g_spc[row];
    bool act = slot < cnt;
    float v = 0.f; int m = 0;
    if (act) {
        v = 0.35f * g_spv[row * 16 + slot];
        m = g_spi[row * 16 + slot];
    }
    int b = row >> 11, n = row & 2047;
    size_t base = (size_t)b * 2048 * 2048;
    const size_t OFF = (size_t)BB * NN * NN;
    if (act) {
        atomicAdd(&out[OFF + base + (size_t)n * 2048 + m],  v);
        atomicAdd(&out[OFF + base + (size_t)m * 2048 + n],  v);
        atomicAdd(&out[base + (size_t)n * 2048 + m], -v);
        atomicAdd(&out[base + (size_t)m * 2048 + n], -v);
        atomicAdd(&g_degsp[(b << 11) + m], v);
    }
    // half-warp (16 aligned lanes = one row) reduce for the row-side degree
    float s = v;
    s += __shfl_xor_sync(0xffffffffu, s, 8);
    s += __shfl_xor_sync(0xffffffffu, s, 4);
    s += __shfl_xor_sync(0xffffffffu, s, 2);
    s += __shfl_xor_sync(0xffffffffu, s, 1);
    if (slot == 0) atomicAdd(&g_degsp[row], s);
}

// ---------------------------------------------------------------------------
// Kernel C3: L[n][n] = degree - A_final[n][n].
// ---------------------------------------------------------------------------
__global__ __launch_bounds__(32) void k_diag(float* __restrict__ out)
{
    const size_t OFF = (size_t)BB * NN * NN;
    int gid = blockIdx.x * 32 + threadIdx.x;     // b*2048+n
    int n = gid & 2047;
    float deg = g_deg[gid] + g_degsp[gid];
    size_t rb = (size_t)gid * 2048;
    float af = out[OFF + rb + n];
    out[rb + n] = deg - af;
}

// ---------------------------------------------------------------------------
extern "C" void kernel_launch(void* const* d_in, const int* in_sizes, int n_in,
                              void* d_out, int out_size)
{
    const float* xd = (const float*)d_in[0];
    const float* xs = (const float*)d_in[1];
    const float* Ap = (const float*)d_in[2];
    const float* Wd = (const float*)d_in[3];
    const float* bd = (const float*)d_in[4];
    const float* Ws = (const float*)d_in[5];
    const float* bs = (const float*)d_in[6];
    const float* Wf = (const float*)d_in[7];
    const float* bf = (const float*)d_in[8];
    const float* Wq = (const float*)d_in[9];
    const float* Wk = (const float*)d_in[10];
    float* out = (float*)d_out;

    const int SMEM_B = (16 * ASTRIDE + 2 * 16 * 17 + 16) * (int)sizeof(float);
    cudaFuncSetAttribute(k_attn, cudaFuncAttributeMaxDynamicSharedMemorySize, SMEM_B);

    k_encode<<<256, 256>>>(xd, xs, Wd, bd, Ws, bs, Wf, bf, Wq, Wk);
    k_frag<<<768, 256>>>();
    k_attn<<<512, 512, SMEM_B>>>(Ap, out);
    k_scatter<<<512, 256>>>(out);
    k_diag<<<256, 32>>>(out);
}

// round 13
// speedup vs baseline: 1.1145x; 1.1145x over previous
#include <cuda_runtime.h>
#include <cuda_bf16.h>

#define BB 4
#define NN 2048
#define TOPK 10

typedef unsigned long long u64;
typedef unsigned int u32;

// Scratch (device globals — no allocation in kernel_launch)
__device__ __align__(128) float g_deg  [BB * NN];     // 0.3*rowsum(prior)
__device__ __align__(128) float g_degsp[BB * NN];     // sparse degree contributions
__device__ __align__(128) float g_spv[BB * NN * 16];  // sparse values
__device__ __align__(128) int   g_spi[BB * NN * 16];  // sparse col indices
__device__ __align__(128) int   g_spc[BB * NN];       // sparse counts
// mma fragments: A (q) hi/lo: [b][rb(128)][h][lane] ; B (k): [b][h][NT(256)][lane]
__device__ __align__(128) uint4 g_qa_hi[4 * 128 * 4 * 32];
__device__ __align__(128) uint4 g_qa_lo[4 * 128 * 4 * 32];
__device__ __align__(128) uint4 g_kb  [4 * 4 * 256 * 32];

__device__ __forceinline__ void mma_bf16(float& d0, float& d1, float& d2, float& d3,
                                         u32 a0, u32 a1, u32 a2, u32 a3,
                                         u32 b0, u32 b1)
{
    asm volatile(
        "mma.sync.aligned.m16n8k16.row.col.f32.bf16.bf16.f32 "
        "{%0,%1,%2,%3},{%4,%5,%6,%7},{%8,%9},{%0,%1,%2,%3};"
        : "+f"(d0), "+f"(d1), "+f"(d2), "+f"(d3)
        : "r"(a0), "r"(a1), "r"(a2), "r"(a3), "r"(b0), "r"(b1));
}
__device__ __forceinline__ float ex2(float x) {
    float r; asm("ex2.approx.f32 %0, %1;" : "=f"(r) : "f"(x));
    return r;
}
__device__ __forceinline__ u32 redux_min_u32(u32 x) {
    u32 r; asm("redux.sync.min.u32 %0, %1, 0xffffffff;" : "=r"(r) : "r"(x));
    return r;
}
__device__ __forceinline__ void bsplit(float x, unsigned short& h, unsigned short& l) {
    __nv_bfloat16 bh = __float2bfloat16(x);
    h = __bfloat16_as_ushort(bh);
    l = __bfloat16_as_ushort(__float2bfloat16(x - __bfloat162float(bh)));
}
__device__ __forceinline__ u32 pk(unsigned short a, unsigned short b) {
    return (u32)a | ((u32)b << 16);
}

// ---------------------------------------------------------------------------
// Kernel A (encoders + fusion + Q/K + FUSED fragment packing).
// 512 threads = 16 warps = 16 nodes = one A-fragment row-block (rb=blockIdx).
// Phase 1 (R11-proven shape, 1 warp = 1 node): encode -> q (pre-scaled by
// 0.25*log2e) and k into smem. Phase 2: warps 0-3 pack A-frags (h=w, hi+lo),
// warps 4-11 pack B-frags (2 NT x 4 h). Deletes the separate k_frag kernel
// and the g_q/g_k global round-trip; fragment bytes are bit-identical.
// ---------------------------------------------------------------------------
__global__ __launch_bounds__(512) void k_encode(
    const float* __restrict__ xd, const float* __restrict__ xs,
    const float* __restrict__ Wd, const float* __restrict__ bd,
    const float* __restrict__ Ws, const float* __restrict__ bs,
    const float* __restrict__ Wf, const float* __restrict__ bf,
    const float* __restrict__ Wq, const float* __restrict__ Wk)
{
    __shared__ float xm_s[16][16];
    __shared__ float cat_s[16][128];
    __shared__ float h_s[16][64];
    __shared__ float q_s[16][64];     // pre-scaled by 0.25*log2(e)
    __shared__ float k_s[16][64];

    int tid = threadIdx.x, w = tid >> 5, l = tid & 31;
    int rb = blockIdx.x & 127, b = blockIdx.x >> 7;
    int node = blockIdx.x * 16 + w;   // == (b*2048) + rb*16 + w

    if (l == 0) g_degsp[node] = 0.f;

    const float* xp = xd + (size_t)node * 512;
    {
        int dd = l & 15, hh = l >> 4;
        float s = 0.f;
        #pragma unroll
        for (int t = hh; t < 32; t += 2) s += xp[t * 16 + dd];
        s += __shfl_xor_sync(0xffffffffu, s, 16);
        if (l < 16) xm_s[w][l] = s * (1.0f / 32.0f);
    }
    __syncwarp();

    float h1a = bd[l], h1b = bd[l + 32];
    #pragma unroll
    for (int d = 0; d < 16; ++d) {
        float x = xm_s[w][d];
        h1a += x * Wd[d * 64 + l];
        h1b += x * Wd[d * 64 + l + 32];
    }
    cat_s[w][l]      = fmaxf(h1a, 0.f);
    cat_s[w][l + 32] = fmaxf(h1b, 0.f);

    float h2a = bs[l], h2b = bs[l + 32];
    const float* xsp = xs + (size_t)node * 8;
    #pragma unroll
    for (int d = 0; d < 8; ++d) {
        float x = xsp[d];
        h2a += x * Ws[d * 64 + l];
        h2b += x * Ws[d * 64 + l + 32];
    }
    cat_s[w][64 + l] = fmaxf(h2a, 0.f);
    cat_s[w][96 + l] = fmaxf(h2b, 0.f);
    __syncwarp();

    float ha = bf[l], hb = bf[l + 32];
    #pragma unroll 8
    for (int i = 0; i < 128; ++i) {
        float c = cat_s[w][i];
        ha += c * Wf[i * 64 + l];
        hb += c * Wf[i * 64 + l + 32];
    }
    h_s[w][l] = ha; h_s[w][l + 32] = hb;
    __syncwarp();

    float qa = 0.f, qb = 0.f, k1 = 0.f, k2 = 0.f;
    #pragma unroll 8
    for (int i = 0; i < 64; ++i) {
        float hv = h_s[w][i];
        qa += hv * Wq[i * 64 + l];
        qb += hv * Wq[i * 64 + l + 32];
        k1 += hv * Wk[i * 64 + l];
        k2 += hv * Wk[i * 64 + l + 32];
    }
    const float sc = 0.25f * 1.4426950408889634f;
    q_s[w][l]      = qa * sc;
    q_s[w][l + 32] = qb * sc;
    k_s[w][l]      = k1;
    k_s[w][l + 32] = k2;
    __syncthreads();

    // ---- phase 2: fragment packing from smem ----
    if (w < 4) {
        // A fragment for (b, rb, h=w): lanes cover 16 rows x 16 k
        int h = w;
        int g = l >> 2, k0 = (l & 3) * 2;
        const float* q0 = &q_s[g][h * 16];
        const float* q1 = &q_s[g + 8][h * 16];
        unsigned short hh[8], ll[8];
        bsplit(q0[k0],     hh[0], ll[0]); bsplit(q0[k0 + 1], hh[1], ll[1]);
        bsplit(q1[k0],     hh[2], ll[2]); bsplit(q1[k0 + 1], hh[3], ll[3]);
        bsplit(q0[k0 + 8], hh[4], ll[4]); bsplit(q0[k0 + 9], hh[5], ll[5]);
        bsplit(q1[k0 + 8], hh[6], ll[6]); bsplit(q1[k0 + 9], hh[7], ll[7]);
        uint4 H, L;
        H.x = pk(hh[0], hh[1]); H.y = pk(hh[2], hh[3]);
        H.z = pk(hh[4], hh[5]); H.w = pk(hh[6], hh[7]);
        L.x = pk(ll[0], ll[1]); L.y = pk(ll[2], ll[3]);
        L.z = pk(ll[4], ll[5]); L.w = pk(ll[6], ll[7]);
        int idx = (((b * 128 + rb) * 4 + h) << 5) + l;
        g_qa_hi[idx] = H; g_qa_lo[idx] = L;
    } else if (w < 12) {
        // B fragment for (b, h, NT): h=(w-4)>>1, NT=rb*2+((w-4)&1)
        int h = (w - 4) >> 1;
        int ntl = (w - 4) & 1;
        int row = ntl * 8 + (l >> 2), k0 = (l & 3) * 2;
        const float* kp = &k_s[row][h * 16];
        unsigned short hh[4], ll[4];
        bsplit(kp[k0],     hh[0], ll[0]); bsplit(kp[k0 + 1], hh[1], ll[1]);
        bsplit(kp[k0 + 8], hh[2], ll[2]); bsplit(kp[k0 + 9], hh[3], ll[3]);
        uint4 V;
        V.x = pk(hh[0], hh[1]); V.y = pk(hh[2], hh[3]);
        V.z = pk(ll[0], ll[1]); V.w = pk(ll[2], ll[3]);
        g_kb[(((b * 4 + h) * 256 + rb * 2 + ntl) << 5) + l] = V;
    }
}

// ---------------------------------------------------------------------------
// Kernel B (attention + FUSED blend): 16 rows/block, 512 threads, lb(512,1).
// Per head: MMA (bf16 hi/lo) + ex2 once; ONE barrier per head; every warp
// redundantly computes all 16 row sums. After each head's Arow update, warp w
// streams a quarter of prior row (n0+w): af = 0.3*prior -> A_final, L=-af,
// accumulating 0.3*rowsum(prior). Top-10 per row in u32 domain + redux.sync.
// ---------------------------------------------------------------------------
#define ASTRIDE 2056
__global__ __launch_bounds__(512, 1) void k_attn(
    const float* __restrict__ prior, float* __restrict__ outp)
{
    extern __shared__ float smem[];
    float* Arow = smem;                          // 16 * 2056
    float* red  = smem + 16 * ASTRIDE;           // 2 buffers * 16 rows * 17
    int*   scnt = (int*)(red + 2 * 16 * 17);     // 16

    int tid = threadIdx.x, w = tid >> 5, l = tid & 31;
    int g = l >> 2, tig = l & 3;
    int b  = blockIdx.x >> 7;
    int rb = blockIdx.x & 127;
    int n0 = rb * 16;

    int qidx = (((b * 128 + rb) * 4) << 5) + l;
    const uint4* kb0 = g_kb + (((b * 4) * 256 + w * 16) << 5) + l;

    const size_t OFF = (size_t)BB * NN * NN;
    size_t rowbase = ((size_t)(b * 2048 + n0 + w)) * 2048;
    const float4* pr4 = (const float4*)(prior + rowbase) + l;
    float4* oA4 = (float4*)(outp + OFF + rowbase) + l;
    float4* oL4 = (float4*)(outp + rowbase) + l;
    float psum = 0.f;                            // 0.3*rowsum(prior) partial

    if (tid < 16) scnt[tid] = 0;

    #pragma unroll 1
    for (int h = 0; h < 4; ++h) {
        uint4 AH = g_qa_hi[qidx + (h << 5)];
        uint4 AL = g_qa_lo[qidx + (h << 5)];
        const uint4* kbp = kb0 + ((h * 256) << 5);

        float acc[64];
        #pragma unroll
        for (int t = 0; t < 16; ++t) {
            uint4 BV = kbp[t << 5];
            float d0 = 0.f, d1 = 0.f, d2 = 0.f, d3 = 0.f;
            mma_bf16(d0, d1, d2, d3, AH.x, AH.y, AH.z, AH.w, BV.x, BV.y);
            mma_bf16(d0, d1, d2, d3, AH.x, AH.y, AH.z, AH.w, BV.z, BV.w);
            mma_bf16(d0, d1, d2, d3, AL.x, AL.y, AL.z, AL.w, BV.x, BV.y);
            acc[t*4]   = d0; acc[t*4+1] = d1;
            acc[t*4+2] = d2; acc[t*4+3] = d3;
        }

        // exp2 + per-row partial sums
        float rsl = 0.f, rsh = 0.f;
        #pragma unroll
        for (int t = 0; t < 16; ++t) {
            float e0 = ex2(acc[t*4]),   e1 = ex2(acc[t*4+1]);
            float e2 = ex2(acc[t*4+2]), e3 = ex2(acc[t*4+3]);
            acc[t*4] = e0; acc[t*4+1] = e1; acc[t*4+2] = e2; acc[t*4+3] = e3;
            rsl += e0 + e1; rsh += e2 + e3;
        }
        rsl += __shfl_xor_sync(0xffffffffu, rsl, 1);
        rsl += __shfl_xor_sync(0xffffffffu, rsl, 2);
        rsh += __shfl_xor_sync(0xffffffffu, rsh, 1);
        rsh += __shfl_xor_sync(0xffffffffu, rsh, 2);
        float* rbuf = red + (h & 1) * 272;       // 16 rows * 17
        if (tig == 0) {
            rbuf[g * 17 + w]       = rsl;
            rbuf[(g + 8) * 17 + w] = rsh;
        }
        __syncthreads();                          // the ONLY barrier this head

        // every warp: lane l computes sum of row (l & 15) via fixed tree
        float invl, invh;
        {
            const float* rp = rbuf + (l & 15) * 17;
            float s0 = rp[0]  + rp[1],  s1 = rp[2]  + rp[3];
            float s2 = rp[4]  + rp[5],  s3 = rp[6]  + rp[7];
            float s4 = rp[8]  + rp[9],  s5 = rp[10] + rp[11];
            float s6 = rp[12] + rp[13], s7 = rp[14] + rp[15];
            s0 += s1; s2 += s3; s4 += s5; s6 += s7;
            s0 += s2; s4 += s6;
            float sv = 0.25f / (s0 + s4);        // 1/4 head-average folded in
            invl = __shfl_sync(0xffffffffu, sv, g);
            invh = __shfl_sync(0xffffffffu, sv, g + 8);
        }

        float2* A2 = (float2*)Arow;              // row stride 1028 float2
        if (h == 0) {
            #pragma unroll
            for (int t = 0; t < 16; ++t) {
                int c2 = w * 64 + t * 4 + tig;
                A2[g * 1028 + c2]       = make_float2(acc[t*4]   * invl, acc[t*4+1] * invl);
                A2[(g + 8) * 1028 + c2] = make_float2(acc[t*4+2] * invh, acc[t*4+3] * invh);
            }
        } else {
            #pragma unroll
            for (int t = 0; t < 16; ++t) {
                int c2 = w * 64 + t * 4 + tig;
                float2 lo = A2[g * 1028 + c2];
                float2 hi = A2[(g + 8) * 1028 + c2];
                lo.x += acc[t*4]   * invl; lo.y += acc[t*4+1] * invl;
                hi.x += acc[t*4+2] * invh; hi.y += acc[t*4+3] * invh;
                A2[g * 1028 + c2]       = lo;
                A2[(g + 8) * 1028 + c2] = hi;
            }
        }

        // ---- fused blend: quarter of prior row (n0+w), cols [h*512, h*512+512)
        {
            int cbase = h * 128;                 // float4 index base of chunk
            #pragma unroll
            for (int i = 0; i < 4; ++i) {
                int c = cbase + i * 32;
                float4 p = pr4[c];
                float4 af = make_float4(0.3f * p.x, 0.3f * p.y,
                                        0.3f * p.z, 0.3f * p.w);
                oA4[c] = af;
                oL4[c] = make_float4(-af.x, -af.y, -af.z, -af.w);
                psum += (af.x + af.y) + (af.z + af.w);
            }
        }
    }

    // degree = 0.3*rowsum(prior): warp-local deterministic reduce
    #pragma unroll
    for (int off = 16; off; off >>= 1)
        psum += __shfl_xor_sync(0xffffffffu, psum, off);
    if (l == 0) g_deg[b * 2048 + n0 + w] = psum;

    __syncthreads();                              // Arow complete for all warps

    // ---- warp w: top-10 of row w in u32 order-isomorphic domain ----
    u32 vi[64];
    const u32* Au = (const u32*)(Arow + w * ASTRIDE);
    #pragma unroll
    for (int i = 0; i < 64; ++i) vi[i] = Au[i * 32 + l];

    u32 c = 0xFFFFFFFFu;
    #pragma unroll 1
    for (int t = 0; t < TOPK; ++t) {
        u32 m0 = 0xFFFFFFFFu, m1 = 0xFFFFFFFFu;
        u32 m2 = 0xFFFFFFFFu, m3 = 0xFFFFFFFFu;
        #pragma unroll
        for (int j = 0; j < 16; ++j) {
            m0 = min(m0, c - vi[4*j+0]);
            m1 = min(m1, c - vi[4*j+1]);
            m2 = min(m2, c - vi[4*j+2]);
            m3 = min(m3, c - vi[4*j+3]);
        }
        u32 dm = redux_min_u32(min(min(m0, m1), min(m2, m3)));
        c = (c - dm) - 1;                        // c = t-th largest - 1
    }
    u32 thr_u = c + 1;                           // 10th-largest bits

    // ---- sparse emit ----
    int row = b * 2048 + n0 + w;
    #pragma unroll
    for (int i = 0; i < 64; ++i) {
        u32 x = vi[i];
        if (x >= thr_u) {
            int p = atomicAdd(&scnt[w], 1);
            if (p < 16) {
                g_spv[row * 16 + p] = __uint_as_float(x);
                g_spi[row * 16 + p] = i * 32 + l;
            }
        }
    }
    __syncwarp();
    if (l == 0) g_spc[row] = min(scnt[w], 16);
}

// ---------------------------------------------------------------------------
// Kernel C2: scatter sparse symmetric contributions into A_final, L, degree.
// Row-side degree contributions reduced across the 16 slot-lanes (aligned
// half-warp) to a single atomicAdd.
// ---------------------------------------------------------------------------
__global__ __launch_bounds__(256) void k_scatter(float* __restrict__ out)
{
    int t = blockIdx.x * 256 + threadIdx.x;      // 131072 = 8192 rows * 16
    int row = t >> 4, slot = t & 15;
    int cnt = g_spc[row];
    bool act = slot < cnt;
    float v = 0.f; int m = 0;
    if (act) {
        v = 0.35f * g_spv[row * 16 + slot];
        m = g_spi[row * 16 + slot];
    }
    int b = row >> 11, n = row & 2047;
    size_t base = (size_t)b * 2048 * 2048;
    const size_t OFF = (size_t)BB * NN * NN;
    if (act) {
        atomicAdd(&out[OFF + base + (size_t)n * 2048 + m],  v);
        atomicAdd(&out[OFF + base + (size_t)m * 2048 + n],  v);
        atomicAdd(&out[base + (size_t)n * 2048 + m], -v);
        atomicAdd(&out[base + (size_t)m * 2048 + n], -v);
        atomicAdd(&g_degsp[(b << 11) + m], v);
    }
    float s = v;
    s += __shfl_xor_sync(0xffffffffu, s, 8);
    s += __shfl_xor_sync(0xffffffffu, s, 4);
    s += __shfl_xor_sync(0xffffffffu, s, 2);
    s += __shfl_xor_sync(0xffffffffu, s, 1);
    if (slot == 0) atomicAdd(&g_degsp[row], s);
}

// ---------------------------------------------------------------------------
// Kernel C3: L[n][n] = degree - A_final[n][n].
// ---------------------------------------------------------------------------
__global__ __launch_bounds__(32) void k_diag(float* __restrict__ out)
{
    const size_t OFF = (size_t)BB * NN * NN;
    int gid = blockIdx.x * 32 + threadIdx.x;     // b*2048+n
    int n = gid & 2047;
    float deg = g_deg[gid] + g_degsp[gid];
    size_t rb = (size_t)gid * 2048;
    float af = out[OFF + rb + n];
    out[rb + n] = deg - af;
}

// ---------------------------------------------------------------------------
extern "C" void kernel_launch(void* const* d_in, const int* in_sizes, int n_in,
                              void* d_out, int out_size)
{
    const float* xd = (const float*)d_in[0];
    const float* xs = (const float*)d_in[1];
    const float* Ap = (const float*)d_in[2];
    const float* Wd = (const float*)d_in[3];
    const float* bd = (const float*)d_in[4];
    const float* Ws = (const float*)d_in[5];
    const float* bs = (const float*)d_in[6];
    const float* Wf = (const float*)d_in[7];
    const float* bf = (const float*)d_in[8];
    const float* Wq = (const float*)d_in[9];
    const float* Wk = (const float*)d_in[10];
    float* out = (float*)d_out;

    const int SMEM_B = (16 * ASTRIDE + 2 * 16 * 17 + 16) * (int)sizeof(float);
    cudaFuncSetAttribute(k_attn, cudaFuncAttributeMaxDynamicSharedMemorySize, SMEM_B);

    k_encode<<<512, 512>>>(xd, xs, Wd, bd, Ws, bs, Wf, bf, Wq, Wk);
    k_attn<<<512, 512, SMEM_B>>>(Ap, out);
    k_scatter<<<512, 256>>>(out);
    k_diag<<<256, 32>>>(out);
}

// round 14
// speedup vs baseline: 1.1296x; 1.0136x over previous
#include <cuda_runtime.h>
#include <cuda_bf16.h>

#define BB 4
#define NN 2048
#define TOPK 10

typedef unsigned long long u64;
typedef unsigned int u32;

// Scratch (device globals — no allocation in kernel_launch)
__device__ __align__(128) float g_deg  [BB * NN];     // 0.3*rowsum(prior)
__device__ __align__(128) float g_degsp[BB * NN];     // sparse degree contributions
__device__ __align__(128) float g_spv[BB * NN * 16];  // sparse values
__device__ __align__(128) int   g_spi[BB * NN * 16];  // sparse col indices
__device__ __align__(128) int   g_spc[BB * NN];       // sparse counts
// mma fragments: A (q) hi/lo: [b][rb(128)][h][lane] ; B (k): [b][h][NT(256)][lane]
__device__ __align__(128) uint4 g_qa_hi[4 * 128 * 4 * 32];
__device__ __align__(128) uint4 g_qa_lo[4 * 128 * 4 * 32];
__device__ __align__(128) uint4 g_kb  [4 * 4 * 256 * 32];

__device__ __forceinline__ void mma_bf16(float& d0, float& d1, float& d2, float& d3,
                                         u32 a0, u32 a1, u32 a2, u32 a3,
                                         u32 b0, u32 b1)
{
    asm volatile(
        "mma.sync.aligned.m16n8k16.row.col.f32.bf16.bf16.f32 "
        "{%0,%1,%2,%3},{%4,%5,%6,%7},{%8,%9},{%0,%1,%2,%3};"
        : "+f"(d0), "+f"(d1), "+f"(d2), "+f"(d3)
        : "r"(a0), "r"(a1), "r"(a2), "r"(a3), "r"(b0), "r"(b1));
}
__device__ __forceinline__ float ex2(float x) {
    float r; asm("ex2.approx.f32 %0, %1;" : "=f"(r) : "f"(x));
    return r;
}
__device__ __forceinline__ u32 redux_min_u32(u32 x) {
    u32 r; asm("redux.sync.min.u32 %0, %1, 0xffffffff;" : "=r"(r) : "r"(x));
    return r;
}
__device__ __forceinline__ void bsplit(float x, unsigned short& h, unsigned short& l) {
    __nv_bfloat16 bh = __float2bfloat16(x);
    h = __bfloat16_as_ushort(bh);
    l = __bfloat16_as_ushort(__float2bfloat16(x - __bfloat162float(bh)));
}
__device__ __forceinline__ u32 pk(unsigned short a, unsigned short b) {
    return (u32)a | ((u32)b << 16);
}

// ---------------------------------------------------------------------------
// Kernel A (encoders + fusion + Q/K + FUSED fragment packing).
// 512 threads = 16 warps = 16 nodes = one A-fragment row-block (rb=blockIdx).
// Weight loads are float2-vectorized: lane l produces output columns (2l,
// 2l+1) from one LDG.64 — halves the per-warp LDG issue count (this kernel
// is LSU-issue-bound). Per-column FFMA order over d is unchanged, so the
// outputs are bit-identical to the scalar version.
// Phase 2: warps 0-3 pack A-frags (h=w), warps 4-11 pack B-frags.
// ---------------------------------------------------------------------------
__global__ __launch_bounds__(512) void k_encode(
    const float* __restrict__ xd, const float* __restrict__ xs,
    const float* __restrict__ Wd, const float* __restrict__ bd,
    const float* __restrict__ Ws, const float* __restrict__ bs,
    const float* __restrict__ Wf, const float* __restrict__ bf,
    const float* __restrict__ Wq, const float* __restrict__ Wk)
{
    __shared__ float xm_s[16][16];
    __shared__ float cat_s[16][128];
    __shared__ float h_s[16][64];
    __shared__ float q_s[16][64];     // pre-scaled by 0.25*log2(e)
    __shared__ float k_s[16][64];

    int tid = threadIdx.x, w = tid >> 5, l = tid & 31;
    int rb = blockIdx.x & 127, b = blockIdx.x >> 7;
    int node = blockIdx.x * 16 + w;   // == (b*2048) + rb*16 + w

    if (l == 0) g_degsp[node] = 0.f;

    const float* xp = xd + (size_t)node * 512;
    {
        int dd = l & 15, hh = l >> 4;
        float s = 0.f;
        #pragma unroll
        for (int t = hh; t < 32; t += 2) s += xp[t * 16 + dd];
        s += __shfl_xor_sync(0xffffffffu, s, 16);
        if (l < 16) xm_s[w][l] = s * (1.0f / 32.0f);
    }
    __syncwarp();

    const float2* Wd2 = (const float2*)Wd;
    const float2* Ws2 = (const float2*)Ws;
    const float2* Wf2 = (const float2*)Wf;
    const float2* Wq2 = (const float2*)Wq;
    const float2* Wk2 = (const float2*)Wk;

    // temporal encoder: lane l -> cols (2l, 2l+1)
    {
        float2 bv = ((const float2*)bd)[l];
        float h1a = bv.x, h1b = bv.y;
        #pragma unroll
        for (int d = 0; d < 16; ++d) {
            float x = xm_s[w][d];
            float2 wv = Wd2[d * 32 + l];
            h1a += x * wv.x;
            h1b += x * wv.y;
        }
        cat_s[w][2 * l]     = fmaxf(h1a, 0.f);
        cat_s[w][2 * l + 1] = fmaxf(h1b, 0.f);
    }

    // static encoder: lane l -> cols (64+2l, 64+2l+1)
    {
        float2 bv = ((const float2*)bs)[l];
        float h2a = bv.x, h2b = bv.y;
        const float* xsp = xs + (size_t)node * 8;
        #pragma unroll
        for (int d = 0; d < 8; ++d) {
            float x = xsp[d];
            float2 wv = Ws2[d * 32 + l];
            h2a += x * wv.x;
            h2b += x * wv.y;
        }
        cat_s[w][64 + 2 * l]     = fmaxf(h2a, 0.f);
        cat_s[w][64 + 2 * l + 1] = fmaxf(h2b, 0.f);
    }
    __syncwarp();

    // fusion: lane l -> cols (2l, 2l+1)
    float ha, hb;
    {
        float2 bv = ((const float2*)bf)[l];
        ha = bv.x; hb = bv.y;
        #pragma unroll 8
        for (int i = 0; i < 128; ++i) {
            float c = cat_s[w][i];
            float2 wv = Wf2[i * 32 + l];
            ha += c * wv.x;
            hb += c * wv.y;
        }
        h_s[w][2 * l]     = ha;
        h_s[w][2 * l + 1] = hb;
    }
    __syncwarp();

    // q = h@Wq, k = h@Wk: lane l -> cols (2l, 2l+1)
    {
        float qa = 0.f, qb = 0.f, k1 = 0.f, k2 = 0.f;
        #pragma unroll 8
        for (int i = 0; i < 64; ++i) {
            float hv = h_s[w][i];
            float2 wq = Wq2[i * 32 + l];
            float2 wk = Wk2[i * 32 + l];
            qa += hv * wq.x; qb += hv * wq.y;
            k1 += hv * wk.x; k2 += hv * wk.y;
        }
        const float sc = 0.25f * 1.4426950408889634f;
        ((float2*)&q_s[w][0])[l] = make_float2(qa * sc, qb * sc);
        ((float2*)&k_s[w][0])[l] = make_float2(k1, k2);
    }
    __syncthreads();

    // ---- phase 2: fragment packing from smem ----
    if (w < 4) {
        // A fragment for (b, rb, h=w): lanes cover 16 rows x 16 k
        int h = w;
        int g = l >> 2, k0 = (l & 3) * 2;
        const float* q0 = &q_s[g][h * 16];
        const float* q1 = &q_s[g + 8][h * 16];
        unsigned short hh[8], ll[8];
        bsplit(q0[k0],     hh[0], ll[0]); bsplit(q0[k0 + 1], hh[1], ll[1]);
        bsplit(q1[k0],     hh[2], ll[2]); bsplit(q1[k0 + 1], hh[3], ll[3]);
        bsplit(q0[k0 + 8], hh[4], ll[4]); bsplit(q0[k0 + 9], hh[5], ll[5]);
        bsplit(q1[k0 + 8], hh[6], ll[6]); bsplit(q1[k0 + 9], hh[7], ll[7]);
        uint4 H, L;
        H.x = pk(hh[0], hh[1]); H.y = pk(hh[2], hh[3]);
        H.z = pk(hh[4], hh[5]); H.w = pk(hh[6], hh[7]);
        L.x = pk(ll[0], ll[1]); L.y = pk(ll[2], ll[3]);
        L.z = pk(ll[4], ll[5]); L.w = pk(ll[6], ll[7]);
        int idx = (((b * 128 + rb) * 4 + h) << 5) + l;
        g_qa_hi[idx] = H; g_qa_lo[idx] = L;
    } else if (w < 12) {
        // B fragment for (b, h, NT): h=(w-4)>>1, NT=rb*2+((w-4)&1)
        int h = (w - 4) >> 1;
        int ntl = (w - 4) & 1;
        int row = ntl * 8 + (l >> 2), k0 = (l & 3) * 2;
        const float* kp = &k_s[row][h * 16];
        unsigned short hh[4], ll[4];
        bsplit(kp[k0],     hh[0], ll[0]); bsplit(kp[k0 + 1], hh[1], ll[1]);
        bsplit(kp[k0 + 8], hh[2], ll[2]); bsplit(kp[k0 + 9], hh[3], ll[3]);
        uint4 V;
        V.x = pk(hh[0], hh[1]); V.y = pk(hh[2], hh[3]);
        V.z = pk(ll[0], ll[1]); V.w = pk(ll[2], ll[3]);
        g_kb[(((b * 4 + h) * 256 + rb * 2 + ntl) << 5) + l] = V;
    }
}

// ---------------------------------------------------------------------------
// Kernel B (attention + FUSED blend): 16 rows/block, 512 threads, lb(512,1).
// Per head: MMA (bf16 hi/lo) + ex2 once; ONE barrier per head; every warp
// redundantly computes all 16 row sums. After each head's Arow update, warp w
// streams a quarter of prior row (n0+w): af = 0.3*prior -> A_final, L=-af,
// accumulating 0.3*rowsum(prior). Top-10 per row in u32 domain + redux.sync.
// ---------------------------------------------------------------------------
#define ASTRIDE 2056
__global__ __launch_bounds__(512, 1) void k_attn(
    const float* __restrict__ prior, float* __restrict__ outp)
{
    extern __shared__ float smem[];
    float* Arow = smem;                          // 16 * 2056
    float* red  = smem + 16 * ASTRIDE;           // 2 buffers * 16 rows * 17
    int*   scnt = (int*)(red + 2 * 16 * 17);     // 16

    int tid = threadIdx.x, w = tid >> 5, l = tid & 31;
    int g = l >> 2, tig = l & 3;
    int b  = blockIdx.x >> 7;
    int rb = blockIdx.x & 127;
    int n0 = rb * 16;

    int qidx = (((b * 128 + rb) * 4) << 5) + l;
    const uint4* kb0 = g_kb + (((b * 4) * 256 + w * 16) << 5) + l;

    const size_t OFF = (size_t)BB * NN * NN;
    size_t rowbase = ((size_t)(b * 2048 + n0 + w)) * 2048;
    const float4* pr4 = (const float4*)(prior + rowbase) + l;
    float4* oA4 = (float4*)(outp + OFF + rowbase) + l;
    float4* oL4 = (float4*)(outp + rowbase) + l;
    float psum = 0.f;                            // 0.3*rowsum(prior) partial

    if (tid < 16) scnt[tid] = 0;

    #pragma unroll 1
    for (int h = 0; h < 4; ++h) {
        uint4 AH = g_qa_hi[qidx + (h << 5)];
        uint4 AL = g_qa_lo[qidx + (h << 5)];
        const uint4* kbp = kb0 + ((h * 256) << 5);

        float acc[64];
        #pragma unroll
        for (int t = 0; t < 16; ++t) {
            uint4 BV = kbp[t << 5];
            float d0 = 0.f, d1 = 0.f, d2 = 0.f, d3 = 0.f;
            mma_bf16(d0, d1, d2, d3, AH.x, AH.y, AH.z, AH.w, BV.x, BV.y);
            mma_bf16(d0, d1, d2, d3, AH.x, AH.y, AH.z, AH.w, BV.z, BV.w);
            mma_bf16(d0, d1, d2, d3, AL.x, AL.y, AL.z, AL.w, BV.x, BV.y);
            acc[t*4]   = d0; acc[t*4+1] = d1;
            acc[t*4+2] = d2; acc[t*4+3] = d3;
        }

        // exp2 + per-row partial sums
        float rsl = 0.f, rsh = 0.f;
        #pragma unroll
        for (int t = 0; t < 16; ++t) {
            float e0 = ex2(acc[t*4]),   e1 = ex2(acc[t*4+1]);
            float e2 = ex2(acc[t*4+2]), e3 = ex2(acc[t*4+3]);
            acc[t*4] = e0; acc[t*4+1] = e1; acc[t*4+2] = e2; acc[t*4+3] = e3;
            rsl += e0 + e1; rsh += e2 + e3;
        }
        rsl += __shfl_xor_sync(0xffffffffu, rsl, 1);
        rsl += __shfl_xor_sync(0xffffffffu, rsl, 2);
        rsh += __shfl_xor_sync(0xffffffffu, rsh, 1);
        rsh += __shfl_xor_sync(0xffffffffu, rsh, 2);
        float* rbuf = red + (h & 1) * 272;       // 16 rows * 17
        if (tig == 0) {
            rbuf[g * 17 + w]       = rsl;
            rbuf[(g + 8) * 17 + w] = rsh;
        }
        __syncthreads();                          // the ONLY barrier this head

        // every warp: lane l computes sum of row (l & 15) via fixed tree
        float invl, invh;
        {
            const float* rp = rbuf + (l & 15) * 17;
            float s0 = rp[0]  + rp[1],  s1 = rp[2]  + rp[3];
            float s2 = rp[4]  + rp[5],  s3 = rp[6]  + rp[7];
            float s4 = rp[8]  + rp[9],  s5 = rp[10] + rp[11];
            float s6 = rp[12] + rp[13], s7 = rp[14] + rp[15];
            s0 += s1; s2 += s3; s4 += s5; s6 += s7;
            s0 += s2; s4 += s6;
            float sv = 0.25f / (s0 + s4);        // 1/4 head-average folded in
            invl = __shfl_sync(0xffffffffu, sv, g);
            invh = __shfl_sync(0xffffffffu, sv, g + 8);
        }

        float2* A2 = (float2*)Arow;              // row stride 1028 float2
        if (h == 0) {
            #pragma unroll
            for (int t = 0; t < 16; ++t) {
                int c2 = w * 64 + t * 4 + tig;
                A2[g * 1028 + c2]       = make_float2(acc[t*4]   * invl, acc[t*4+1] * invl);
                A2[(g + 8) * 1028 + c2] = make_float2(acc[t*4+2] * invh, acc[t*4+3] * invh);
            }
        } else {
            #pragma unroll
            for (int t = 0; t < 16; ++t) {
                int c2 = w * 64 + t * 4 + tig;
                float2 lo = A2[g * 1028 + c2];
                float2 hi = A2[(g + 8) * 1028 + c2];
                lo.x += acc[t*4]   * invl; lo.y += acc[t*4+1] * invl;
                hi.x += acc[t*4+2] * invh; hi.y += acc[t*4+3] * invh;
                A2[g * 1028 + c2]       = lo;
                A2[(g + 8) * 1028 + c2] = hi;
            }
        }

        // ---- fused blend: quarter of prior row (n0+w), cols [h*512, h*512+512)
        {
            int cbase = h * 128;                 // float4 index base of chunk
            #pragma unroll
            for (int i = 0; i < 4; ++i) {
                int c = cbase + i * 32;
                float4 p = pr4[c];
                float4 af = make_float4(0.3f * p.x, 0.3f * p.y,
                                        0.3f * p.z, 0.3f * p.w);
                oA4[c] = af;
                oL4[c] = make_float4(-af.x, -af.y, -af.z, -af.w);
                psum += (af.x + af.y) + (af.z + af.w);
            }
        }
    }

    // degree = 0.3*rowsum(prior): warp-local deterministic reduce
    #pragma unroll
    for (int off = 16; off; off >>= 1)
        psum += __shfl_xor_sync(0xffffffffu, psum, off);
    if (l == 0) g_deg[b * 2048 + n0 + w] = psum;

    __syncthreads();                              // Arow complete for all warps

    // ---- warp w: top-10 of row w in u32 order-isomorphic domain ----
    u32 vi[64];
    const u32* Au = (const u32*)(Arow + w * ASTRIDE);
    #pragma unroll
    for (int i = 0; i < 64; ++i) vi[i] = Au[i * 32 + l];

    u32 c = 0xFFFFFFFFu;
    #pragma unroll 1
    for (int t = 0; t < TOPK; ++t) {
        u32 m0 = 0xFFFFFFFFu, m1 = 0xFFFFFFFFu;
        u32 m2 = 0xFFFFFFFFu, m3 = 0xFFFFFFFFu;
        #pragma unroll
        for (int j = 0; j < 16; ++j) {
            m0 = min(m0, c - vi[4*j+0]);
            m1 = min(m1, c - vi[4*j+1]);
            m2 = min(m2, c - vi[4*j+2]);
            m3 = min(m3, c - vi[4*j+3]);
        }
        u32 dm = redux_min_u32(min(min(m0, m1), min(m2, m3)));
        c = (c - dm) - 1;                        // c = t-th largest - 1
    }
    u32 thr_u = c + 1;                           // 10th-largest bits

    // ---- sparse emit ----
    int row = b * 2048 + n0 + w;
    #pragma unroll
    for (int i = 0; i < 64; ++i) {
        u32 x = vi[i];
        if (x >= thr_u) {
            int p = atomicAdd(&scnt[w], 1);
            if (p < 16) {
                g_spv[row * 16 + p] = __uint_as_float(x);
                g_spi[row * 16 + p] = i * 32 + l;
            }
        }
    }
    __syncwarp();
    if (l == 0) g_spc[row] = min(scnt[w], 16);
}

// ---------------------------------------------------------------------------
// Kernel C2: scatter sparse symmetric contributions into A_final, L, degree.
// Row-side degree contributions reduced across the 16 slot-lanes (aligned
// half-warp) to a single atomicAdd.
// ---------------------------------------------------------------------------
__global__ __launch_bounds__(256) void k_scatter(float* __restrict__ out)
{
    int t = blockIdx.x * 256 + threadIdx.x;      // 131072 = 8192 rows * 16
    int row = t >> 4, slot = t & 15;
    int cnt = g_spc[row];
    bool act = slot < cnt;
    float v = 0.f; int m = 0;
    if (act) {
        v = 0.35f * g_spv[row * 16 + slot];
        m = g_spi[row * 16 + slot];
    }
    int b = row >> 11, n = row & 2047;
    size_t base = (size_t)b * 2048 * 2048;
    const size_t OFF = (size_t)BB * NN * NN;
    if (act) {
        atomicAdd(&out[OFF + base + (size_t)n * 2048 + m],  v);
        atomicAdd(&out[OFF + base + (size_t)m * 2048 + n],  v);
        atomicAdd(&out[base + (size_t)n * 2048 + m], -v);
        atomicAdd(&out[base + (size_t)m * 2048 + n], -v);
        atomicAdd(&g_degsp[(b << 11) + m], v);
    }
    float s = v;
    s += __shfl_xor_sync(0xffffffffu, s, 8);
    s += __shfl_xor_sync(0xffffffffu, s, 4);
    s += __shfl_xor_sync(0xffffffffu, s, 2);
    s += __shfl_xor_sync(0xffffffffu, s, 1);
    if (slot == 0) atomicAdd(&g_degsp[row], s);
}

// ---------------------------------------------------------------------------
// Kernel C3: L[n][n] = degree - A_final[n][n].
// ---------------------------------------------------------------------------
__global__ __launch_bounds__(32) void k_diag(float* __restrict__ out)
{
    const size_t OFF = (size_t)BB * NN * NN;
    int gid = blockIdx.x * 32 + threadIdx.x;     // b*2048+n
    int n = gid & 2047;
    float deg = g_deg[gid] + g_degsp[gid];
    size_t rb = (size_t)gid * 2048;
    float af = out[OFF + rb + n];
    out[rb + n] = deg - af;
}

// ---------------------------------------------------------------------------
extern "C" void kernel_launch(void* const* d_in, const int* in_sizes, int n_in,
                              void* d_out, int out_size)
{
    const float* xd = (const float*)d_in[0];
    const float* xs = (const float*)d_in[1];
    const float* Ap = (const float*)d_in[2];
    const float* Wd = (const float*)d_in[3];
    const float* bd = (const float*)d_in[4];
    const float* Ws = (const float*)d_in[5];
    const float* bs = (const float*)d_in[6];
    const float* Wf = (const float*)d_in[7];
    const float* bf = (const float*)d_in[8];
    const float* Wq = (const float*)d_in[9];
    const float* Wk = (const float*)d_in[10];
    float* out = (float*)d_out;

    const int SMEM_B = (16 * ASTRIDE + 2 * 16 * 17 + 16) * (int)sizeof(float);
    cudaFuncSetAttribute(k_attn, cudaFuncAttributeMaxDynamicSharedMemorySize, SMEM_B);

    k_encode<<<512, 512>>>(xd, xs, Wd, bd, Ws, bs, Wf, bf, Wq, Wk);
    k_attn<<<512, 512, SMEM_B>>>(Ap, out);
    k_scatter<<<512, 256>>>(out);
    k_diag<<<256, 32>>>(out);
}

// round 15
// speedup vs baseline: 1.1847x; 1.0488x over previous
#include <cuda_runtime.h>
#include <cuda_bf16.h>

#define BB 4
#define NN 2048
#define TOPK 10

typedef unsigned long long u64;
typedef unsigned int u32;

// Scratch (device globals — no allocation in kernel_launch)
__device__ __align__(128) float g_deg  [BB * NN];     // 0.3*rowsum(prior)
__device__ __align__(128) float g_degsp[BB * NN];     // sparse degree contributions
__device__ __align__(128) float g_spv[BB * NN * 16];  // sparse values (padded: v=0)
__device__ __align__(128) int   g_spi[BB * NN * 16];  // sparse col indices (padded: diag)
// mma fragments: A (q) hi/lo: [b][rb(128)][h][lane] ; B (k, hi only): [b][h][NT(256)][lane]
__device__ __align__(128) uint4 g_qa_hi[4 * 128 * 4 * 32];
__device__ __align__(128) uint4 g_qa_lo[4 * 128 * 4 * 32];
__device__ __align__(128) uint2 g_kb  [4 * 4 * 256 * 32];

__device__ __forceinline__ void mma_bf16(float& d0, float& d1, float& d2, float& d3,
                                         u32 a0, u32 a1, u32 a2, u32 a3,
                                         u32 b0, u32 b1)
{
    asm volatile(
        "mma.sync.aligned.m16n8k16.row.col.f32.bf16.bf16.f32 "
        "{%0,%1,%2,%3},{%4,%5,%6,%7},{%8,%9},{%0,%1,%2,%3};"
        : "+f"(d0), "+f"(d1), "+f"(d2), "+f"(d3)
        : "r"(a0), "r"(a1), "r"(a2), "r"(a3), "r"(b0), "r"(b1));
}
__device__ __forceinline__ float ex2(float x) {
    float r; asm("ex2.approx.f32 %0, %1;" : "=f"(r) : "f"(x));
    return r;
}
__device__ __forceinline__ u32 redux_min_u32(u32 x) {
    u32 r; asm("redux.sync.min.u32 %0, %1, 0xffffffff;" : "=r"(r) : "r"(x));
    return r;
}
__device__ __forceinline__ void bsplit(float x, unsigned short& h, unsigned short& l) {
    __nv_bfloat16 bh = __float2bfloat16(x);
    h = __bfloat16_as_ushort(bh);
    l = __bfloat16_as_ushort(__float2bfloat16(x - __bfloat162float(bh)));
}
__device__ __forceinline__ unsigned short bhi(float x) {
    return __bfloat16_as_ushort(__float2bfloat16(x));
}
__device__ __forceinline__ u32 pk(unsigned short a, unsigned short b) {
    return (u32)a | ((u32)b << 16);
}

// ---------------------------------------------------------------------------
// Kernel A (encoders + fusion + Q/K + FUSED fragment packing).
// 512 threads = 16 warps = 16 nodes = one A-fragment row-block (rb=blockIdx).
// Weight loads float2-vectorized (lane l -> output cols 2l, 2l+1).
// Phase 2: warps 0-3 pack A-frags (q hi+lo), warps 4-11 pack B-frags (k hi
// only — the q*k_lo correction term is dropped; error ~2e-4 on A entries,
// orders of magnitude inside the 1e-3 budget).
// ---------------------------------------------------------------------------
__global__ __launch_bounds__(512) void k_encode(
    const float* __restrict__ xd, const float* __restrict__ xs,
    const float* __restrict__ Wd, const float* __restrict__ bd,
    const float* __restrict__ Ws, const float* __restrict__ bs,
    const float* __restrict__ Wf, const float* __restrict__ bf,
    const float* __restrict__ Wq, const float* __restrict__ Wk)
{
    __shared__ float xm_s[16][16];
    __shared__ float cat_s[16][128];
    __shared__ float h_s[16][64];
    __shared__ float q_s[16][64];     // pre-scaled by 0.25*log2(e)
    __shared__ float k_s[16][64];

    int tid = threadIdx.x, w = tid >> 5, l = tid & 31;
    int rb = blockIdx.x & 127, b = blockIdx.x >> 7;
    int node = blockIdx.x * 16 + w;   // == (b*2048) + rb*16 + w

    if (l == 0) g_degsp[node] = 0.f;

    const float* xp = xd + (size_t)node * 512;
    {
        int dd = l & 15, hh = l >> 4;
        float s = 0.f;
        #pragma unroll
        for (int t = hh; t < 32; t += 2) s += xp[t * 16 + dd];
        s += __shfl_xor_sync(0xffffffffu, s, 16);
        if (l < 16) xm_s[w][l] = s * (1.0f / 32.0f);
    }
    __syncwarp();

    const float2* Wd2 = (const float2*)Wd;
    const float2* Ws2 = (const float2*)Ws;
    const float2* Wf2 = (const float2*)Wf;
    const float2* Wq2 = (const float2*)Wq;
    const float2* Wk2 = (const float2*)Wk;

    // temporal encoder: lane l -> cols (2l, 2l+1)
    {
        float2 bv = ((const float2*)bd)[l];
        float h1a = bv.x, h1b = bv.y;
        #pragma unroll
        for (int d = 0; d < 16; ++d) {
            float x = xm_s[w][d];
            float2 wv = Wd2[d * 32 + l];
            h1a += x * wv.x;
            h1b += x * wv.y;
        }
        cat_s[w][2 * l]     = fmaxf(h1a, 0.f);
        cat_s[w][2 * l + 1] = fmaxf(h1b, 0.f);
    }

    // static encoder: lane l -> cols (64+2l, 64+2l+1)
    {
        float2 bv = ((const float2*)bs)[l];
        float h2a = bv.x, h2b = bv.y;
        const float* xsp = xs + (size_t)node * 8;
        #pragma unroll
        for (int d = 0; d < 8; ++d) {
            float x = xsp[d];
            float2 wv = Ws2[d * 32 + l];
            h2a += x * wv.x;
            h2b += x * wv.y;
        }
        cat_s[w][64 + 2 * l]     = fmaxf(h2a, 0.f);
        cat_s[w][64 + 2 * l + 1] = fmaxf(h2b, 0.f);
    }
    __syncwarp();

    // fusion: lane l -> cols (2l, 2l+1)
    {
        float2 bv = ((const float2*)bf)[l];
        float ha = bv.x, hb = bv.y;
        #pragma unroll 8
        for (int i = 0; i < 128; ++i) {
            float c = cat_s[w][i];
            float2 wv = Wf2[i * 32 + l];
            ha += c * wv.x;
            hb += c * wv.y;
        }
        h_s[w][2 * l]     = ha;
        h_s[w][2 * l + 1] = hb;
    }
    __syncwarp();

    // q = h@Wq, k = h@Wk: lane l -> cols (2l, 2l+1)
    {
        float qa = 0.f, qb = 0.f, k1 = 0.f, k2 = 0.f;
        #pragma unroll 8
        for (int i = 0; i < 64; ++i) {
            float hv = h_s[w][i];
            float2 wq = Wq2[i * 32 + l];
            float2 wk = Wk2[i * 32 + l];
            qa += hv * wq.x; qb += hv * wq.y;
            k1 += hv * wk.x; k2 += hv * wk.y;
        }
        const float sc = 0.25f * 1.4426950408889634f;
        ((float2*)&q_s[w][0])[l] = make_float2(qa * sc, qb * sc);
        ((float2*)&k_s[w][0])[l] = make_float2(k1, k2);
    }
    __syncthreads();

    // ---- phase 2: fragment packing from smem ----
    if (w < 4) {
        // A fragment for (b, rb, h=w): lanes cover 16 rows x 16 k
        int h = w;
        int g = l >> 2, k0 = (l & 3) * 2;
        const float* q0 = &q_s[g][h * 16];
        const float* q1 = &q_s[g + 8][h * 16];
        unsigned short hh[8], ll[8];
        bsplit(q0[k0],     hh[0], ll[0]); bsplit(q0[k0 + 1], hh[1], ll[1]);
        bsplit(q1[k0],     hh[2], ll[2]); bsplit(q1[k0 + 1], hh[3], ll[3]);
        bsplit(q0[k0 + 8], hh[4], ll[4]); bsplit(q0[k0 + 9], hh[5], ll[5]);
        bsplit(q1[k0 + 8], hh[6], ll[6]); bsplit(q1[k0 + 9], hh[7], ll[7]);
        uint4 H, L;
        H.x = pk(hh[0], hh[1]); H.y = pk(hh[2], hh[3]);
        H.z = pk(hh[4], hh[5]); H.w = pk(hh[6], hh[7]);
        L.x = pk(ll[0], ll[1]); L.y = pk(ll[2], ll[3]);
        L.z = pk(ll[4], ll[5]); L.w = pk(ll[6], ll[7]);
        int idx = (((b * 128 + rb) * 4 + h) << 5) + l;
        g_qa_hi[idx] = H; g_qa_lo[idx] = L;
    } else if (w < 12) {
        // B fragment (hi only) for (b, h, NT): h=(w-4)>>1, NT=rb*2+((w-4)&1)
        int h = (w - 4) >> 1;
        int ntl = (w - 4) & 1;
        int row = ntl * 8 + (l >> 2), k0 = (l & 3) * 2;
        const float* kp = &k_s[row][h * 16];
        uint2 V;
        V.x = pk(bhi(kp[k0]),     bhi(kp[k0 + 1]));
        V.y = pk(bhi(kp[k0 + 8]), bhi(kp[k0 + 9]));
        g_kb[(((b * 4 + h) * 256 + rb * 2 + ntl) << 5) + l] = V;
    }
}

// ---------------------------------------------------------------------------
// Kernel B (attention + FUSED blend): 16 rows/block, 512 threads, lb(512,1).
// Per head: 2-pass MMA ((q_hi+q_lo)*k_hi) + ex2 once; ONE barrier per head;
// every warp redundantly computes all 16 row sums. After each head's Arow
// update, warp w streams a quarter of prior row: af = 0.3*prior -> A_final,
// L=-af, accumulating 0.3*rowsum(prior). u32-domain top-10 + redux.sync.
// Unused sparse slots are padded (v=0, m=diag) so k_scatter is branch-free.
// ---------------------------------------------------------------------------
#define ASTRIDE 2056
__global__ __launch_bounds__(512, 1) void k_attn(
    const float* __restrict__ prior, float* __restrict__ outp)
{
    extern __shared__ float smem[];
    float* Arow = smem;                          // 16 * 2056
    float* red  = smem + 16 * ASTRIDE;           // 2 buffers * 16 rows * 17
    int*   scnt = (int*)(red + 2 * 16 * 17);     // 16

    int tid = threadIdx.x, w = tid >> 5, l = tid & 31;
    int g = l >> 2, tig = l & 3;
    int b  = blockIdx.x >> 7;
    int rb = blockIdx.x & 127;
    int n0 = rb * 16;

    int qidx = (((b * 128 + rb) * 4) << 5) + l;
    const uint2* kb0 = g_kb + (((b * 4) * 256 + w * 16) << 5) + l;

    const size_t OFF = (size_t)BB * NN * NN;
    size_t rowbase = ((size_t)(b * 2048 + n0 + w)) * 2048;
    const float4* pr4 = (const float4*)(prior + rowbase) + l;
    float4* oA4 = (float4*)(outp + OFF + rowbase) + l;
    float4* oL4 = (float4*)(outp + rowbase) + l;
    float psum = 0.f;                            // 0.3*rowsum(prior) partial

    if (tid < 16) scnt[tid] = 0;

    #pragma unroll 1
    for (int h = 0; h < 4; ++h) {
        uint4 AH = g_qa_hi[qidx + (h << 5)];
        uint4 AL = g_qa_lo[qidx + (h << 5)];
        const uint2* kbp = kb0 + ((h * 256) << 5);

        float acc[64];
        #pragma unroll
        for (int t = 0; t < 16; ++t) {
            uint2 BV = kbp[t << 5];
            float d0 = 0.f, d1 = 0.f, d2 = 0.f, d3 = 0.f;
            mma_bf16(d0, d1, d2, d3, AH.x, AH.y, AH.z, AH.w, BV.x, BV.y);
            mma_bf16(d0, d1, d2, d3, AL.x, AL.y, AL.z, AL.w, BV.x, BV.y);
            acc[t*4]   = d0; acc[t*4+1] = d1;
            acc[t*4+2] = d2; acc[t*4+3] = d3;
        }

        // exp2 + per-row partial sums
        float rsl = 0.f, rsh = 0.f;
        #pragma unroll
        for (int t = 0; t < 16; ++t) {
            float e0 = ex2(acc[t*4]),   e1 = ex2(acc[t*4+1]);
            float e2 = ex2(acc[t*4+2]), e3 = ex2(acc[t*4+3]);
            acc[t*4] = e0; acc[t*4+1] = e1; acc[t*4+2] = e2; acc[t*4+3] = e3;
            rsl += e0 + e1; rsh += e2 + e3;
        }
        rsl += __shfl_xor_sync(0xffffffffu, rsl, 1);
        rsl += __shfl_xor_sync(0xffffffffu, rsl, 2);
        rsh += __shfl_xor_sync(0xffffffffu, rsh, 1);
        rsh += __shfl_xor_sync(0xffffffffu, rsh, 2);
        float* rbuf = red + (h & 1) * 272;       // 16 rows * 17
        if (tig == 0) {
            rbuf[g * 17 + w]       = rsl;
            rbuf[(g + 8) * 17 + w] = rsh;
        }
        __syncthreads();                          // the ONLY barrier this head

        // every warp: lane l computes sum of row (l & 15) via fixed tree
        float invl, invh;
        {
            const float* rp = rbuf + (l & 15) * 17;
            float s0 = rp[0]  + rp[1],  s1 = rp[2]  + rp[3];
            float s2 = rp[4]  + rp[5],  s3 = rp[6]  + rp[7];
            float s4 = rp[8]  + rp[9],  s5 = rp[10] + rp[11];
            float s6 = rp[12] + rp[13], s7 = rp[14] + rp[15];
            s0 += s1; s2 += s3; s4 += s5; s6 += s7;
            s0 += s2; s4 += s6;
            float sv = 0.25f / (s0 + s4);        // 1/4 head-average folded in
            invl = __shfl_sync(0xffffffffu, sv, g);
            invh = __shfl_sync(0xffffffffu, sv, g + 8);
        }

        float2* A2 = (float2*)Arow;              // row stride 1028 float2
        if (h == 0) {
            #pragma unroll
            for (int t = 0; t < 16; ++t) {
                int c2 = w * 64 + t * 4 + tig;
                A2[g * 1028 + c2]       = make_float2(acc[t*4]   * invl, acc[t*4+1] * invl);
                A2[(g + 8) * 1028 + c2] = make_float2(acc[t*4+2] * invh, acc[t*4+3] * invh);
            }
        } else {
            #pragma unroll
            for (int t = 0; t < 16; ++t) {
                int c2 = w * 64 + t * 4 + tig;
                float2 lo = A2[g * 1028 + c2];
                float2 hi = A2[(g + 8) * 1028 + c2];
                lo.x += acc[t*4]   * invl; lo.y += acc[t*4+1] * invl;
                hi.x += acc[t*4+2] * invh; hi.y += acc[t*4+3] * invh;
                A2[g * 1028 + c2]       = lo;
                A2[(g + 8) * 1028 + c2] = hi;
            }
        }

        // ---- fused blend: quarter of prior row (n0+w), cols [h*512, h*512+512)
        {
            int cbase = h * 128;                 // float4 index base of chunk
            #pragma unroll
            for (int i = 0; i < 4; ++i) {
                int c = cbase + i * 32;
                float4 p = pr4[c];
                float4 af = make_float4(0.3f * p.x, 0.3f * p.y,
                                        0.3f * p.z, 0.3f * p.w);
                oA4[c] = af;
                oL4[c] = make_float4(-af.x, -af.y, -af.z, -af.w);
                psum += (af.x + af.y) + (af.z + af.w);
            }
        }
    }

    // degree = 0.3*rowsum(prior): warp-local deterministic reduce
    #pragma unroll
    for (int off = 16; off; off >>= 1)
        psum += __shfl_xor_sync(0xffffffffu, psum, off);
    if (l == 0) g_deg[b * 2048 + n0 + w] = psum;

    __syncthreads();                              // Arow complete for all warps

    // ---- warp w: top-10 of row w in u32 order-isomorphic domain ----
    u32 vi[64];
    const u32* Au = (const u32*)(Arow + w * ASTRIDE);
    #pragma unroll
    for (int i = 0; i < 64; ++i) vi[i] = Au[i * 32 + l];

    u32 c = 0xFFFFFFFFu;
    #pragma unroll 1
    for (int t = 0; t < TOPK; ++t) {
        u32 m0 = 0xFFFFFFFFu, m1 = 0xFFFFFFFFu;
        u32 m2 = 0xFFFFFFFFu, m3 = 0xFFFFFFFFu;
        #pragma unroll
        for (int j = 0; j < 16; ++j) {
            m0 = min(m0, c - vi[4*j+0]);
            m1 = min(m1, c - vi[4*j+1]);
            m2 = min(m2, c - vi[4*j+2]);
            m3 = min(m3, c - vi[4*j+3]);
        }
        u32 dm = redux_min_u32(min(min(m0, m1), min(m2, m3)));
        c = (c - dm) - 1;                        // c = t-th largest - 1
    }
    u32 thr_u = c + 1;                           // 10th-largest bits

    // ---- sparse emit + slot padding (branch-free scatter downstream) ----
    int row = b * 2048 + n0 + w;
    #pragma unroll
    for (int i = 0; i < 64; ++i) {
        u32 x = vi[i];
        if (x >= thr_u) {
            int p = atomicAdd(&scnt[w], 1);
            if (p < 16) {
                g_spv[row * 16 + p] = __uint_as_float(x);
                g_spi[row * 16 + p] = i * 32 + l;
            }
        }
    }
    __syncwarp();
    int cnt = min(scnt[w], 16);
    if (l >= cnt && l < 16) {                    // pad: v=0 at own diagonal
        g_spv[row * 16 + l] = 0.f;
        g_spi[row * 16 + l] = n0 + w;
    }
}

// ---------------------------------------------------------------------------
// Kernel C2: scatter sparse symmetric contributions into A_final, L, degree.
// Branch-free (slots padded with v=0); row-side degree reduced across the
// 16 slot-lanes to a single atomicAdd.
// ---------------------------------------------------------------------------
__global__ __launch_bounds__(256) void k_scatter(float* __restrict__ out)
{
    int t = blockIdx.x * 256 + threadIdx.x;      // 131072 = 8192 rows * 16
    int row = t >> 4, slot = t & 15;
    float v = 0.35f * g_spv[row * 16 + slot];
    int m = g_spi[row * 16 + slot];
    int b = row >> 11, n = row & 2047;
    size_t base = (size_t)b * 2048 * 2048;
    const size_t OFF = (size_t)BB * NN * NN;
    atomicAdd(&out[OFF + base + (size_t)n * 2048 + m],  v);
    atomicAdd(&out[OFF + base + (size_t)m * 2048 + n],  v);
    atomicAdd(&out[base + (size_t)n * 2048 + m], -v);
    atomicAdd(&out[base + (size_t)m * 2048 + n], -v);
    atomicAdd(&g_degsp[(b << 11) + m], v);
    float s = v;
    s += __shfl_xor_sync(0xffffffffu, s, 8);
    s += __shfl_xor_sync(0xffffffffu, s, 4);
    s += __shfl_xor_sync(0xffffffffu, s, 2);
    s += __shfl_xor_sync(0xffffffffu, s, 1);
    if (slot == 0) atomicAdd(&g_degsp[row], s);
}

// ---------------------------------------------------------------------------
// Kernel C3: L[n][n] = degree - A_final[n][n].
// ---------------------------------------------------------------------------
__global__ __launch_bounds__(32) void k_diag(float* __restrict__ out)
{
    const size_t OFF = (size_t)BB * NN * NN;
    int gid = blockIdx.x * 32 + threadIdx.x;     // b*2048+n
    int n = gid & 2047;
    float deg = g_deg[gid] + g_degsp[gid];
    size_t rb = (size_t)gid * 2048;
    float af = out[OFF + rb + n];
    out[rb + n] = deg - af;
}

// ---------------------------------------------------------------------------
extern "C" void kernel_launch(void* const* d_in, const int* in_sizes, int n_in,
                              void* d_out, int out_size)
{
    const float* xd = (const float*)d_in[0];
    const float* xs = (const float*)d_in[1];
    const float* Ap = (const float*)d_in[2];
    const float* Wd = (const float*)d_in[3];
    const float* bd = (const float*)d_in[4];
    const float* Ws = (const float*)d_in[5];
    const float* bs = (const float*)d_in[6];
    const float* Wf = (const float*)d_in[7];
    const float* bf = (const float*)d_in[8];
    const float* Wq = (const float*)d_in[9];
    const float* Wk = (const float*)d_in[10];
    float* out = (float*)d_out;

    const int SMEM_B = (16 * ASTRIDE + 2 * 16 * 17 + 16) * (int)sizeof(float);
    cudaFuncSetAttribute(k_attn, cudaFuncAttributeMaxDynamicSharedMemorySize, SMEM_B);

    k_encode<<<512, 512>>>(xd, xs, Wd, bd, Ws, bs, Wf, bf, Wq, Wk);
    k_attn<<<512, 512, SMEM_B>>>(Ap, out);
    k_scatter<<<512, 256>>>(out);
    k_diag<<<256, 32>>>(out);
}

// round 16
// speedup vs baseline: 1.2509x; 1.0559x over previous
#include <cuda_runtime.h>
#include <cuda_bf16.h>

#define BB 4
#define NN 2048
#define TOPK 10

typedef unsigned long long u64;
typedef unsigned int u32;

// Scratch (device globals — no allocation in kernel_launch)
__device__ __align__(128) float g_deg  [BB * NN];     // 0.3*rowsum(prior)
__device__ __align__(128) float g_degsp[BB * NN];     // sparse degree contributions
__device__ __align__(128) float g_spv[BB * NN * 16];  // sparse values (padded: v=0)
__device__ __align__(128) int   g_spi[BB * NN * 16];  // sparse col indices (padded: diag)
// mma fragments (bf16, hi only): A (q): [b][rb(128)][h][lane]; B (k): [b][h][NT(256)][lane]
__device__ __align__(128) uint4 g_qa[4 * 128 * 4 * 32];
__device__ __align__(128) uint2 g_kb[4 * 4 * 256 * 32];

__device__ __forceinline__ void mma_bf16(float& d0, float& d1, float& d2, float& d3,
                                         u32 a0, u32 a1, u32 a2, u32 a3,
                                         u32 b0, u32 b1)
{
    asm volatile(
        "mma.sync.aligned.m16n8k16.row.col.f32.bf16.bf16.f32 "
        "{%0,%1,%2,%3},{%4,%5,%6,%7},{%8,%9},{%0,%1,%2,%3};"
        : "+f"(d0), "+f"(d1), "+f"(d2), "+f"(d3)
        : "r"(a0), "r"(a1), "r"(a2), "r"(a3), "r"(b0), "r"(b1));
}
__device__ __forceinline__ float ex2(float x) {
    float r; asm("ex2.approx.f32 %0, %1;" : "=f"(r) : "f"(x));
    return r;
}
__device__ __forceinline__ u32 redux_min_u32(u32 x) {
    u32 r; asm("redux.sync.min.u32 %0, %1, 0xffffffff;" : "=r"(r) : "r"(x));
    return r;
}
__device__ __forceinline__ unsigned short bhi(float x) {
    return __bfloat16_as_ushort(__float2bfloat16(x));
}
__device__ __forceinline__ u32 pk(unsigned short a, unsigned short b) {
    return (u32)a | ((u32)b << 16);
}

// ---------------------------------------------------------------------------
// Kernel A (encoders + fusion + Q/K + FUSED bf16 fragment packing).
// 512 threads = 16 warps = 16 nodes = one A-fragment row-block (rb=blockIdx).
// x_dyn mean is fully coalesced: 4 x LDG.128 per lane + shfl_xor(4,8,16)
// tree (the old 64B-stride scalar loads cost 16x the L1tex wavefronts).
// Weight loads float2-vectorized (lane l -> output cols 2l, 2l+1).
// Phase 2: warps 0-3 pack A-frags, warps 4-11 pack B-frags — both bf16 hi
// only (q_lo and k_lo correction terms dropped; error ~few e-5, inside the
// 1e-3 budget with >15x margin).
// ---------------------------------------------------------------------------
__global__ __launch_bounds__(512) void k_encode(
    const float* __restrict__ xd, const float* __restrict__ xs,
    const float* __restrict__ Wd, const float* __restrict__ bd,
    const float* __restrict__ Ws, const float* __restrict__ bs,
    const float* __restrict__ Wf, const float* __restrict__ bf,
    const float* __restrict__ Wq, const float* __restrict__ Wk)
{
    __shared__ float xm_s[16][16];
    __shared__ float cat_s[16][128];
    __shared__ float h_s[16][64];
    __shared__ float q_s[16][64];     // pre-scaled by 0.25*log2(e)
    __shared__ float k_s[16][64];

    int tid = threadIdx.x, w = tid >> 5, l = tid & 31;
    int rb = blockIdx.x & 127, b = blockIdx.x >> 7;
    int node = blockIdx.x * 16 + w;   // == (b*2048) + rb*16 + w

    if (l == 0) g_degsp[node] = 0.f;

    // coalesced mean over T: x row = 128 float4; lane l takes f = l, l+32,
    // l+64, l+96 (f = t*4 + dg, dg = l&3). Component sums then xor-tree over
    // bits 2..4 -> lanes 0..3 hold the 16 feature sums as one float4 each.
    {
        const float4* xp4 = (const float4*)(xd + (size_t)node * 512);
        float4 a0 = xp4[l], a1 = xp4[l + 32], a2 = xp4[l + 64], a3 = xp4[l + 96];
        float4 sv;
        sv.x = (a0.x + a1.x) + (a2.x + a3.x);
        sv.y = (a0.y + a1.y) + (a2.y + a3.y);
        sv.z = (a0.z + a1.z) + (a2.z + a3.z);
        sv.w = (a0.w + a1.w) + (a2.w + a3.w);
        #pragma unroll
        for (int off = 4; off <= 16; off <<= 1) {
            sv.x += __shfl_xor_sync(0xffffffffu, sv.x, off);
            sv.y += __shfl_xor_sync(0xffffffffu, sv.y, off);
            sv.z += __shfl_xor_sync(0xffffffffu, sv.z, off);
            sv.w += __shfl_xor_sync(0xffffffffu, sv.w, off);
        }
        if (l < 4) {
            const float m = 1.0f / 32.0f;
            ((float4*)&xm_s[w][0])[l] =
                make_float4(sv.x * m, sv.y * m, sv.z * m, sv.w * m);
        }
    }
    __syncwarp();

    const float2* Wd2 = (const float2*)Wd;
    const float2* Ws2 = (const float2*)Ws;
    const float2* Wf2 = (const float2*)Wf;
    const float2* Wq2 = (const float2*)Wq;
    const float2* Wk2 = (const float2*)Wk;

    // temporal encoder: lane l -> cols (2l, 2l+1)
    {
        float2 bv = ((const float2*)bd)[l];
        float h1a = bv.x, h1b = bv.y;
        #pragma unroll
        for (int d = 0; d < 16; ++d) {
            float x = xm_s[w][d];
            float2 wv = Wd2[d * 32 + l];
            h1a += x * wv.x;
            h1b += x * wv.y;
        }
        cat_s[w][2 * l]     = fmaxf(h1a, 0.f);
        cat_s[w][2 * l + 1] = fmaxf(h1b, 0.f);
    }

    // static encoder: lane l -> cols (64+2l, 64+2l+1)
    {
        float2 bv = ((const float2*)bs)[l];
        float h2a = bv.x, h2b = bv.y;
        const float* xsp = xs + (size_t)node * 8;
        #pragma unroll
        for (int d = 0; d < 8; ++d) {
            float x = xsp[d];
            float2 wv = Ws2[d * 32 + l];
            h2a += x * wv.x;
            h2b += x * wv.y;
        }
        cat_s[w][64 + 2 * l]     = fmaxf(h2a, 0.f);
        cat_s[w][64 + 2 * l + 1] = fmaxf(h2b, 0.f);
    }
    __syncwarp();

    // fusion: lane l -> cols (2l, 2l+1)
    {
        float2 bv = ((const float2*)bf)[l];
        float ha = bv.x, hb = bv.y;
        #pragma unroll 8
        for (int i = 0; i < 128; ++i) {
            float c = cat_s[w][i];
            float2 wv = Wf2[i * 32 + l];
            ha += c * wv.x;
            hb += c * wv.y;
        }
        h_s[w][2 * l]     = ha;
        h_s[w][2 * l + 1] = hb;
    }
    __syncwarp();

    // q = h@Wq, k = h@Wk: lane l -> cols (2l, 2l+1)
    {
        float qa = 0.f, qb = 0.f, k1 = 0.f, k2 = 0.f;
        #pragma unroll 8
        for (int i = 0; i < 64; ++i) {
            float hv = h_s[w][i];
            float2 wq = Wq2[i * 32 + l];
            float2 wk = Wk2[i * 32 + l];
            qa += hv * wq.x; qb += hv * wq.y;
            k1 += hv * wk.x; k2 += hv * wk.y;
        }
        const float sc = 0.25f * 1.4426950408889634f;
        ((float2*)&q_s[w][0])[l] = make_float2(qa * sc, qb * sc);
        ((float2*)&k_s[w][0])[l] = make_float2(k1, k2);
    }
    __syncthreads();

    // ---- phase 2: bf16 fragment packing from smem ----
    if (w < 4) {
        // A fragment for (b, rb, h=w): lanes cover 16 rows x 16 k
        int h = w;
        int g = l >> 2, k0 = (l & 3) * 2;
        const float* q0 = &q_s[g][h * 16];
        const float* q1 = &q_s[g + 8][h * 16];
        uint4 H;
        H.x = pk(bhi(q0[k0]),     bhi(q0[k0 + 1]));
        H.y = pk(bhi(q1[k0]),     bhi(q1[k0 + 1]));
        H.z = pk(bhi(q0[k0 + 8]), bhi(q0[k0 + 9]));
        H.w = pk(bhi(q1[k0 + 8]), bhi(q1[k0 + 9]));
        g_qa[(((b * 128 + rb) * 4 + h) << 5) + l] = H;
    } else if (w < 12) {
        // B fragment for (b, h, NT): h=(w-4)>>1, NT=rb*2+((w-4)&1)
        int h = (w - 4) >> 1;
        int ntl = (w - 4) & 1;
        int row = ntl * 8 + (l >> 2), k0 = (l & 3) * 2;
        const float* kp = &k_s[row][h * 16];
        uint2 V;
        V.x = pk(bhi(kp[k0]),     bhi(kp[k0 + 1]));
        V.y = pk(bhi(kp[k0 + 8]), bhi(kp[k0 + 9]));
        g_kb[(((b * 4 + h) * 256 + rb * 2 + ntl) << 5) + l] = V;
    }
}

// ---------------------------------------------------------------------------
// Kernel B (attention + FUSED blend): 16 rows/block, 512 threads, lb(512,1).
// Per head: ONE bf16 MMA per tile + ex2 once; ONE barrier per head; every
// warp redundantly computes all 16 row sums. After each head's Arow update,
// warp w streams a quarter of prior row: af = 0.3*prior -> A_final, L=-af,
// accumulating 0.3*rowsum(prior). u32-domain top-10 + redux.sync.
// Unused sparse slots padded (v=0, m=diag) so k_scatter is branch-free.
// ---------------------------------------------------------------------------
#define ASTRIDE 2056
__global__ __launch_bounds__(512, 1) void k_attn(
    const float* __restrict__ prior, float* __restrict__ outp)
{
    extern __shared__ float smem[];
    float* Arow = smem;                          // 16 * 2056
    float* red  = smem + 16 * ASTRIDE;           // 2 buffers * 16 rows * 17
    int*   scnt = (int*)(red + 2 * 16 * 17);     // 16

    int tid = threadIdx.x, w = tid >> 5, l = tid & 31;
    int g = l >> 2, tig = l & 3;
    int b  = blockIdx.x >> 7;
    int rb = blockIdx.x & 127;
    int n0 = rb * 16;

    int qidx = (((b * 128 + rb) * 4) << 5) + l;
    const uint2* kb0 = g_kb + (((b * 4) * 256 + w * 16) << 5) + l;

    const size_t OFF = (size_t)BB * NN * NN;
    size_t rowbase = ((size_t)(b * 2048 + n0 + w)) * 2048;
    const float4* pr4 = (const float4*)(prior + rowbase) + l;
    float4* oA4 = (float4*)(outp + OFF + rowbase) + l;
    float4* oL4 = (float4*)(outp + rowbase) + l;
    float psum = 0.f;                            // 0.3*rowsum(prior) partial

    if (tid < 16) scnt[tid] = 0;

    #pragma unroll 1
    for (int h = 0; h < 4; ++h) {
        uint4 AH = g_qa[qidx + (h << 5)];
        const uint2* kbp = kb0 + ((h * 256) << 5);

        float acc[64];
        #pragma unroll
        for (int t = 0; t < 16; ++t) {
            uint2 BV = kbp[t << 5];
            float d0 = 0.f, d1 = 0.f, d2 = 0.f, d3 = 0.f;
            mma_bf16(d0, d1, d2, d3, AH.x, AH.y, AH.z, AH.w, BV.x, BV.y);
            acc[t*4]   = d0; acc[t*4+1] = d1;
            acc[t*4+2] = d2; acc[t*4+3] = d3;
        }

        // exp2 + per-row partial sums
        float rsl = 0.f, rsh = 0.f;
        #pragma unroll
        for (int t = 0; t < 16; ++t) {
            float e0 = ex2(acc[t*4]),   e1 = ex2(acc[t*4+1]);
            float e2 = ex2(acc[t*4+2]), e3 = ex2(acc[t*4+3]);
            acc[t*4] = e0; acc[t*4+1] = e1; acc[t*4+2] = e2; acc[t*4+3] = e3;
            rsl += e0 + e1; rsh += e2 + e3;
        }
        rsl += __shfl_xor_sync(0xffffffffu, rsl, 1);
        rsl += __shfl_xor_sync(0xffffffffu, rsl, 2);
        rsh += __shfl_xor_sync(0xffffffffu, rsh, 1);
        rsh += __shfl_xor_sync(0xffffffffu, rsh, 2);
        float* rbuf = red + (h & 1) * 272;       // 16 rows * 17
        if (tig == 0) {
            rbuf[g * 17 + w]       = rsl;
            rbuf[(g + 8) * 17 + w] = rsh;
        }
        __syncthreads();                          // the ONLY barrier this head

        // every warp: lane l computes sum of row (l & 15) via fixed tree
        float invl, invh;
        {
            const float* rp = rbuf + (l & 15) * 17;
            float s0 = rp[0]  + rp[1],  s1 = rp[2]  + rp[3];
            float s2 = rp[4]  + rp[5],  s3 = rp[6]  + rp[7];
            float s4 = rp[8]  + rp[9],  s5 = rp[10] + rp[11];
            float s6 = rp[12] + rp[13], s7 = rp[14] + rp[15];
            s0 += s1; s2 += s3; s4 += s5; s6 += s7;
            s0 += s2; s4 += s6;
            float sv = 0.25f / (s0 + s4);        // 1/4 head-average folded in
            invl = __shfl_sync(0xffffffffu, sv, g);
            invh = __shfl_sync(0xffffffffu, sv, g + 8);
        }

        float2* A2 = (float2*)Arow;              // row stride 1028 float2
        if (h == 0) {
            #pragma unroll
            for (int t = 0; t < 16; ++t) {
                int c2 = w * 64 + t * 4 + tig;
                A2[g * 1028 + c2]       = make_float2(acc[t*4]   * invl, acc[t*4+1] * invl);
                A2[(g + 8) * 1028 + c2] = make_float2(acc[t*4+2] * invh, acc[t*4+3] * invh);
            }
        } else {
            #pragma unroll
            for (int t = 0; t < 16; ++t) {
                int c2 = w * 64 + t * 4 + tig;
                float2 lo = A2[g * 1028 + c2];
                float2 hi = A2[(g + 8) * 1028 + c2];
                lo.x += acc[t*4]   * invl; lo.y += acc[t*4+1] * invl;
                hi.x += acc[t*4+2] * invh; hi.y += acc[t*4+3] * invh;
                A2[g * 1028 + c2]       = lo;
                A2[(g + 8) * 1028 + c2] = hi;
            }
        }

        // ---- fused blend: quarter of prior row (n0+w), cols [h*512, h*512+512)
        {
            int cbase = h * 128;                 // float4 index base of chunk
            #pragma unroll
            for (int i = 0; i < 4; ++i) {
                int c = cbase + i * 32;
                float4 p = pr4[c];
                float4 af = make_float4(0.3f * p.x, 0.3f * p.y,
                                        0.3f * p.z, 0.3f * p.w);
                oA4[c] = af;
                oL4[c] = make_float4(-af.x, -af.y, -af.z, -af.w);
                psum += (af.x + af.y) + (af.z + af.w);
            }
        }
    }

    // degree = 0.3*rowsum(prior): warp-local deterministic reduce
    #pragma unroll
    for (int off = 16; off; off >>= 1)
        psum += __shfl_xor_sync(0xffffffffu, psum, off);
    if (l == 0) g_deg[b * 2048 + n0 + w] = psum;

    __syncthreads();                              // Arow complete for all warps

    // ---- warp w: top-10 of row w in u32 order-isomorphic domain ----
    u32 vi[64];
    const u32* Au = (const u32*)(Arow + w * ASTRIDE);
    #pragma unroll
    for (int i = 0; i < 64; ++i) vi[i] = Au[i * 32 + l];

    u32 c = 0xFFFFFFFFu;
    #pragma unroll 1
    for (int t = 0; t < TOPK; ++t) {
        u32 m0 = 0xFFFFFFFFu, m1 = 0xFFFFFFFFu;
        u32 m2 = 0xFFFFFFFFu, m3 = 0xFFFFFFFFu;
        #pragma unroll
        for (int j = 0; j < 16; ++j) {
            m0 = min(m0, c - vi[4*j+0]);
            m1 = min(m1, c - vi[4*j+1]);
            m2 = min(m2, c - vi[4*j+2]);
            m3 = min(m3, c - vi[4*j+3]);
        }
        u32 dm = redux_min_u32(min(min(m0, m1), min(m2, m3)));
        c = (c - dm) - 1;                        // c = t-th largest - 1
    }
    u32 thr_u = c + 1;                           // 10th-largest bits

    // ---- sparse emit + slot padding (branch-free scatter downstream) ----
    int row = b * 2048 + n0 + w;
    #pragma unroll
    for (int i = 0; i < 64; ++i) {
        u32 x = vi[i];
        if (x >= thr_u) {
            int p = atomicAdd(&scnt[w], 1);
            if (p < 16) {
                g_spv[row * 16 + p] = __uint_as_float(x);
                g_spi[row * 16 + p] = i * 32 + l;
            }
        }
    }
    __syncwarp();
    int cnt = min(scnt[w], 16);
    if (l >= cnt && l < 16) {                    // pad: v=0 at own diagonal
        g_spv[row * 16 + l] = 0.f;
        g_spi[row * 16 + l] = n0 + w;
    }
}

// ---------------------------------------------------------------------------
// Kernel C2: scatter sparse symmetric contributions into A_final, L, degree.
// Branch-free (slots padded with v=0); row-side degree reduced across the
// 16 slot-lanes to a single atomicAdd.
// ---------------------------------------------------------------------------
__global__ __launch_bounds__(256) void k_scatter(float* __restrict__ out)
{
    int t = blockIdx.x * 256 + threadIdx.x;      // 131072 = 8192 rows * 16
    int row = t >> 4, slot = t & 15;
    float v = 0.35f * g_spv[row * 16 + slot];
    int m = g_spi[row * 16 + slot];
    int b = row >> 11, n = row & 2047;
    size_t base = (size_t)b * 2048 * 2048;
    const size_t OFF = (size_t)BB * NN * NN;
    atomicAdd(&out[OFF + base + (size_t)n * 2048 + m],  v);
    atomicAdd(&out[OFF + base + (size_t)m * 2048 + n],  v);
    atomicAdd(&out[base + (size_t)n * 2048 + m], -v);
    atomicAdd(&out[base + (size_t)m * 2048 + n], -v);
    atomicAdd(&g_degsp[(b << 11) + m], v);
    float s = v;
    s += __shfl_xor_sync(0xffffffffu, s, 8);
    s += __shfl_xor_sync(0xffffffffu, s, 4);
    s += __shfl_xor_sync(0xffffffffu, s, 2);
    s += __shfl_xor_sync(0xffffffffu, s, 1);
    if (slot == 0) atomicAdd(&g_degsp[row], s);
}

// ---------------------------------------------------------------------------
// Kernel C3: L[n][n] = degree - A_final[n][n].
// ---------------------------------------------------------------------------
__global__ __launch_bounds__(32) void k_diag(float* __restrict__ out)
{
    const size_t OFF = (size_t)BB * NN * NN;
    int gid = blockIdx.x * 32 + threadIdx.x;     // b*2048+n
    int n = gid & 2047;
    float deg = g_deg[gid] + g_degsp[gid];
    size_t rb = (size_t)gid * 2048;
    float af = out[OFF + rb + n];
    out[rb + n] = deg - af;
}

// ---------------------------------------------------------------------------
extern "C" void kernel_launch(void* const* d_in, const int* in_sizes, int n_in,
                              void* d_out, int out_size)
{
    const float* xd = (const float*)d_in[0];
    const float* xs = (const float*)d_in[1];
    const float* Ap = (const float*)d_in[2];
    const float* Wd = (const float*)d_in[3];
    const float* bd = (const float*)d_in[4];
    const float* Ws = (const float*)d_in[5];
    const float* bs = (const float*)d_in[6];
    const float* Wf = (const float*)d_in[7];
    const float* bf = (const float*)d_in[8];
    const float* Wq = (const float*)d_in[9];
    const float* Wk = (const float*)d_in[10];
    float* out = (float*)d_out;

    const int SMEM_B = (16 * ASTRIDE + 2 * 16 * 17 + 16) * (int)sizeof(float);
    cudaFuncSetAttribute(k_attn, cudaFuncAttributeMaxDynamicSharedMemorySize, SMEM_B);

    k_encode<<<512, 512>>>(xd, xs, Wd, bd, Ws, bs, Wf, bf, Wq, Wk);
    k_attn<<<512, 512, SMEM_B>>>(Ap, out);
    k_scatter<<<512, 256>>>(out);
    k_diag<<<256, 32>>>(out);
}